// round 13
// baseline (speedup 1.0000x reference)
#include <cuda_runtime.h>
#include <cuda_bf16.h>
#include <math.h>

// ----------------------------------------------------------------------------
// Problem constants
// ----------------------------------------------------------------------------
#define Bz   16
#define Nn   392
#define Cc   512
#define Hh   16
#define HD   32
#define Mm   (Bz*Hh)          // 256
#define LF   196              // Nn/2
#define MLPH 2048
#define ROWS (Bz*Nn)          // 6272
#define WROW (Nn*LF)          // 76832  scores per m
#define KSEL 7448             // int(0.1*195)*392
#define NWORD 2401            // WROW/32 mask words per m
#define NEGBIG (-3.4e38f)

// score kernel smem layout
#define KS_BYTES (Nn*8*16)            // 50176: K tile, float4 chunks, swizzled
#define QS_BYTES (8*32*4)             // 1024 : 8 scaled q rows
#define RED_BYTES 128                 // 4 warps x 8 floats
#define SC_SMEM (KS_BYTES + QS_BYTES + RED_BYTES)

// ----------------------------------------------------------------------------
// Scratch (static device globals; no allocation at runtime)
// ----------------------------------------------------------------------------
__device__ float g_h   [ROWS*Cc];
__device__ float g_qkv [ROWS*3*Cc];
__device__ float g_q   [Mm*Nn*HD];
__device__ float g_k   [Mm*Nn*HD];
__device__ float g_v   [Mm*Nn*HD];
__device__ float g_probs[(size_t)Mm*Nn*Nn];     // unmasked softmax probs
__device__ unsigned g_scores[(size_t)Mm*WROW];  // positive-float sort keys
__device__ unsigned g_maskbits[(size_t)Mm*NWORD + 8];
__device__ float g_o   [ROWS*Cc];
__device__ float g_x1  [ROWS*Cc];
__device__ float g_h2  [ROWS*Cc];
__device__ float g_mlp [ROWS*MLPH];

// ----------------------------------------------------------------------------
// Reductions
// ----------------------------------------------------------------------------
__device__ __forceinline__ float warpMax(float v){
  #pragma unroll
  for (int o=16;o>0;o>>=1) v = fmaxf(v, __shfl_xor_sync(0xffffffffu, v, o));
  return v;
}
__device__ __forceinline__ float warpSum(float v){
  #pragma unroll
  for (int o=16;o>0;o>>=1) v += __shfl_xor_sync(0xffffffffu, v, o);
  return v;
}
template<int NW>
__device__ __forceinline__ float blockSum(float v, float* sw){
  int lane = threadIdx.x & 31, w = threadIdx.x >> 5;
  v = warpSum(v);
  if (lane==0) sw[w] = v;
  __syncthreads();
  float r = 0.f;
  #pragma unroll
  for (int i=0;i<NW;i++) r += sw[i];
  __syncthreads();
  return r;
}

// ----------------------------------------------------------------------------
// JAX threefry2x32, key (0,42), partitionable 32-bit path
// ----------------------------------------------------------------------------
__device__ __forceinline__ unsigned rotl32(unsigned x, int r){ return (x<<r)|(x>>(32-r)); }
__device__ __forceinline__ unsigned threefry_bits(unsigned idx){
  const unsigned k0 = 0u, k1 = 42u;
  const unsigned k2 = k0 ^ k1 ^ 0x1BD11BDAu;
  unsigned x0 = 0u + k0;
  unsigned x1 = idx + k1;
#define TFR(r) { x0 += x1; x1 = rotl32(x1,(r)); x1 ^= x0; }
  TFR(13) TFR(15) TFR(26) TFR(6)
  x0 += k1; x1 += k2 + 1u;
  TFR(17) TFR(29) TFR(16) TFR(24)
  x0 += k2; x1 += k0 + 2u;
  TFR(13) TFR(15) TFR(26) TFR(6)
  x0 += k0; x1 += k1 + 3u;
  TFR(17) TFR(29) TFR(16) TFR(24)
  x0 += k1; x1 += k2 + 4u;
  TFR(13) TFR(15) TFR(26) TFR(6)
  x0 += k2; x1 += k0 + 5u;
#undef TFR
  return x0 ^ x1;
}
// returns -ln(u) for the gumbel draw at flat index idx  (1 MUFU log)
__device__ __forceinline__ float neglogu_at(unsigned idx){
  unsigned bits = threefry_bits(idx);
  float f = __uint_as_float((bits >> 9) | 0x3f800000u) - 1.0f;
  const float tiny = 1.17549435e-38f;
  float u = fmaxf(tiny, f + tiny);
  return -__logf(u);
}

// ----------------------------------------------------------------------------
// LayerNorm (one block per row, 256 threads, C=512)
// ----------------------------------------------------------------------------
__global__ void __launch_bounds__(256) ln_kernel(const float* __restrict__ x,
                                                 const float* __restrict__ w,
                                                 const float* __restrict__ bias,
                                                 float* __restrict__ out){
  int row = blockIdx.x, t = threadIdx.x;
  const float* xr = x + (size_t)row*Cc;
  __shared__ float sw[8];
  float a = xr[t], b = xr[t+256];
  float s = blockSum<8>(a+b, sw);
  float mu = s * (1.0f/512.0f);
  float da = a-mu, db = b-mu;
  float v = blockSum<8>(da*da + db*db, sw);
  float rstd = rsqrtf(v*(1.0f/512.0f) + 1e-5f);
  out[(size_t)row*Cc + t]     = da*rstd*w[t]     + bias[t];
  out[(size_t)row*Cc + t+256] = db*rstd*w[t+256] + bias[t+256];
}

// ----------------------------------------------------------------------------
// tf32 tensor-core GEMM: 128x128 tile, BK=16, 256 threads, mma.m16n8k8.tf32,
// cp.async 3-stage pipeline (dynamic smem). Raw fp32 bits fed to tf32 mma.
// act: 0 = bias(+res), 1 = bias+gelu
// ----------------------------------------------------------------------------
__device__ __forceinline__ void cp16(float* dst, const float* src){
  unsigned d = (unsigned)__cvta_generic_to_shared(dst);
  asm volatile("cp.async.ca.shared.global [%0], [%1], 16;\n" :: "r"(d), "l"(src));
}
__device__ __forceinline__ void mma_tf32(float* c, const unsigned* a, const unsigned* b){
  asm volatile(
    "mma.sync.aligned.m16n8k8.row.col.f32.tf32.tf32.f32 "
    "{%0,%1,%2,%3},{%4,%5,%6,%7},{%8,%9},{%0,%1,%2,%3};\n"
    : "+f"(c[0]),"+f"(c[1]),"+f"(c[2]),"+f"(c[3])
    : "r"(a[0]),"r"(a[1]),"r"(a[2]),"r"(a[3]),"r"(b[0]),"r"(b[1]));
}

#define APAD 20
#define BPAD 136
#define AS_STRIDE (128*APAD)          // floats per A stage
#define BS_STRIDE (16*BPAD)           // floats per B stage
#define GEMM_SMEM ((3*AS_STRIDE + 3*BS_STRIDE)*4)   // 56832 bytes

__global__ void __launch_bounds__(256, 2) gemm_tf32(const float* __restrict__ A,
                                                 const float* __restrict__ Bw,
                                                 const float* __restrict__ bias,
                                                 const float* __restrict__ res,
                                                 float* __restrict__ C,
                                                 int M, int N, int K, int act){
  extern __shared__ float gsm[];
  float* Asb = gsm;
  float* Bsb = gsm + 3*AS_STRIDE;
  const int tid = threadIdx.x;
  const int lane = tid & 31, wid = tid >> 5;
  const int wm = wid >> 2, wn = wid & 3;       // 2 x 4 warp grid
  const int bm = blockIdx.y*128, bn = blockIdx.x*128;

  float acc[16][4];
  #pragma unroll
  for (int i=0;i<16;i++){ acc[i][0]=0.f; acc[i][1]=0.f; acc[i][2]=0.f; acc[i][3]=0.f; }

  const int nT = K >> 4;

  auto load_stage = [&](int t, int buf){
    float* As = Asb + buf*AS_STRIDE;
    float* Bs = Bsb + buf*BS_STRIDE;
    int k0 = t << 4;
    #pragma unroll
    for (int r=0;r<2;r++){
      int i = tid + 256*r;
      int arow = i >> 2, ac = (i & 3) << 2;
      cp16(&As[arow*APAD + ac], A + (size_t)(bm+arow)*K + k0 + ac);
      int brow = i >> 5, bc = (i & 31) << 2;
      cp16(&Bs[brow*BPAD + bc], Bw + (size_t)(k0+brow)*N + bn + bc);
    }
    asm volatile("cp.async.commit_group;\n");
  };

  load_stage(0, 0);
  load_stage(1, 1);
  int cbuf = 0;   // compute buffer = t%3
  int lbuf = 2;   // load buffer   = (t+2)%3
  for (int t=0; t<nT; t++){
    if (t+2 < nT) load_stage(t+2, lbuf);
    if (t+2 < nT)      asm volatile("cp.async.wait_group 2;\n");
    else if (t+1 < nT) asm volatile("cp.async.wait_group 1;\n");
    else               asm volatile("cp.async.wait_group 0;\n");
    __syncthreads();
    const unsigned* as = (const unsigned*)(Asb + cbuf*AS_STRIDE);
    const unsigned* bs = (const unsigned*)(Bsb + cbuf*BS_STRIDE);
    #pragma unroll
    for (int ks=0; ks<16; ks+=8){
      unsigned a[4][4], b[4][2];
      #pragma unroll
      for (int mt=0;mt<4;mt++){
        int r0 = wm*64 + mt*16 + (lane>>2);
        int cc = ks + (lane&3);
        a[mt][0] = as[r0*APAD + cc];
        a[mt][1] = as[(r0+8)*APAD + cc];
        a[mt][2] = as[r0*APAD + cc + 4];
        a[mt][3] = as[(r0+8)*APAD + cc + 4];
      }
      #pragma unroll
      for (int nt=0;nt<4;nt++){
        int cn = wn*32 + nt*8 + (lane>>2);
        b[nt][0] = bs[(ks + (lane&3))*BPAD + cn];
        b[nt][1] = bs[(ks + 4 + (lane&3))*BPAD + cn];
      }
      #pragma unroll
      for (int mt=0;mt<4;mt++)
        #pragma unroll
        for (int nt=0;nt<4;nt++)
          mma_tf32(acc[mt*4+nt], a[mt], b[nt]);
    }
    __syncthreads();
    if (++cbuf == 3) cbuf = 0;
    if (++lbuf == 3) lbuf = 0;
  }

  #pragma unroll
  for (int mt=0;mt<4;mt++){
    #pragma unroll
    for (int nt=0;nt<4;nt++){
      float* c = acc[mt*4+nt];
      int gm = bm + wm*64 + mt*16 + (lane>>2);
      int gn = bn + wn*32 + nt*8 + ((lane&3)<<1);
      float b0 = bias[gn], b1 = bias[gn+1];
      #pragma unroll
      for (int hrow=0; hrow<2; hrow++){
        int gr = gm + hrow*8;
        float v0 = c[hrow*2+0] + b0;
        float v1 = c[hrow*2+1] + b1;
        if (act==1){
          v0 = 0.5f*v0*(1.0f + erff(v0*0.70710678118654752440f));
          v1 = 0.5f*v1*(1.0f + erff(v1*0.70710678118654752440f));
        }
        if (res){
          v0 += res[(size_t)gr*N + gn];
          v1 += res[(size_t)gr*N + gn+1];
        }
        C[(size_t)gr*N + gn]   = v0;
        C[(size_t)gr*N + gn+1] = v1;
      }
    }
  }
}

// ----------------------------------------------------------------------------
// QKV reorder: [row=b*392+i][3*512] -> Q/K/V [m=b*16+h][i][d]
// ----------------------------------------------------------------------------
__global__ void reorder_qkv(){
  int idx = blockIdx.x*blockDim.x + threadIdx.x;
  if (idx >= ROWS*3*Cc) return;
  int r = idx / (3*Cc), c = idx % (3*Cc);
  int which = c >> 9;
  int cc = c & 511;
  int h = cc >> 5, d = cc & 31;
  int b = r / Nn, i = r % Nn;
  float v = g_qkv[idx];
  size_t dst = ((size_t)((b*Hh+h)*Nn + i))*HD + d;
  if (which==0) g_q[dst]=v; else if (which==1) g_k[dst]=v; else g_v[dst]=v;
}

// ----------------------------------------------------------------------------
// score kernel v5: block = (m, 8 query rows), 128 threads.
//  - 64 j-slots x 2 row-groups of 4 rows: each K float4 LDS feeds 4 rows
//    (block LDS volume halved vs v4). Logits stay in registers.
//  - K tile staged once in smem, XOR-swizzled chunks (4-phase conflict-free).
//  - stats via 2-warp reductions through a tiny smem pad ([4 warps][8]).
// ----------------------------------------------------------------------------
__global__ void __launch_bounds__(128) score_kernel(){
  extern __shared__ char sraw[];
  float4* ks  = (float4*)sraw;
  float*  qs  = (float*)(sraw + KS_BYTES);
  float*  red = (float*)(sraw + KS_BYTES + QS_BYTES);   // [4 warps][8]

  int blk = blockIdx.x;
  int m = blk / 49, it = blk % 49;
  int i0 = it*8;
  int tid = threadIdx.x, lane = tid & 31;

  // stage q rows (scale folded in): 256 elements, 2 rounds
  #pragma unroll
  for (int rr=0; rr<2; rr++){
    int e = tid + rr*128;
    int i = e >> 5, d = e & 31;
    qs[i*32 + d] = g_q[((size_t)m*Nn + i0 + i)*HD + d] * 0.17677669529663687f;
  }
  // stage K, coalesced read, swizzled store
  const float4* kg = (const float4*)(g_k + (size_t)m*Nn*HD);
  #pragma unroll 1
  for (int c = tid; c < Nn*8; c += 128){
    int j = c >> 3, ch = c & 7;
    ks[(j<<3) | (ch ^ (j & 7))] = kg[c];
  }
  __syncthreads();

  const int rg = tid >> 6;           // 0..1  (row group: rows 4rg..4rg+3)
  const int jslot = tid & 63;        // 0..63
  const int w = tid >> 5;            // 0..3
  const int sw = jslot & 7;
  const int rbase = rg*4;
  const int w0 = rg*2, w1 = rg*2+1;

  // row indices + side info
  int irow[4], same[4];
  #pragma unroll
  for (int r=0;r<4;r++){
    irow[r] = i0 + rbase + r;
    same[r] = (irow[r] >= LF) ? LF : 0;
  }

  // ---- QK dot: 28 register accumulators (4 rows x 7 j-chunks)
  float acc[4][7];
  #pragma unroll
  for (int r=0;r<4;r++)
    #pragma unroll
    for (int jj=0;jj<7;jj++) acc[r][jj]=0.f;

  #pragma unroll
  for (int t=0;t<8;t++){
    float4 q0 = *(const float4*)&qs[(rbase+0)*32 + t*4];
    float4 q1 = *(const float4*)&qs[(rbase+1)*32 + t*4];
    float4 q2 = *(const float4*)&qs[(rbase+2)*32 + t*4];
    float4 q3 = *(const float4*)&qs[(rbase+3)*32 + t*4];
    #pragma unroll
    for (int jj=0;jj<7;jj++){
      int j = jslot + (jj<<6);
      int jbase = (jj<6 || jslot<8) ? j : jslot;    // clamp invalid tail
      float4 kv = ks[(jbase<<3) | (t ^ sw)];
      acc[0][jj] += kv.x*q0.x + kv.y*q0.y + kv.z*q0.z + kv.w*q0.w;
      acc[1][jj] += kv.x*q1.x + kv.y*q1.y + kv.z*q1.z + kv.w*q1.w;
      acc[2][jj] += kv.x*q2.x + kv.y*q2.y + kv.z*q2.z + kv.w*q2.w;
      acc[3][jj] += kv.x*q3.x + kv.y*q3.y + kv.z*q3.z + kv.w*q3.w;
    }
  }

  // ---- round 1: row max + cross-side max
  float lm[4], cm[4];
  #pragma unroll
  for (int r=0;r<4;r++){ lm[r]=NEGBIG; cm[r]=NEGBIG; }
  #pragma unroll
  for (int jj=0;jj<7;jj++){
    int j = jslot + (jj<<6);
    bool v = (jj<6) || (jslot<8);
    if (v){
      #pragma unroll
      for (int r=0;r<4;r++){
        lm[r] = fmaxf(lm[r], acc[r][jj]);
        bool cr = same[r] ? (j<LF) : (j>=LF);
        if (cr) cm[r] = fmaxf(cm[r], acc[r][jj]);
      }
    }
  }
  #pragma unroll
  for (int r=0;r<4;r++){ lm[r]=warpMax(lm[r]); cm[r]=warpMax(cm[r]); }
  if (lane==0){
    #pragma unroll
    for (int r=0;r<4;r++){ red[w*8+r]=lm[r]; red[w*8+4+r]=cm[r]; }
  }
  __syncthreads();
  float mx[4], cx[4];
  #pragma unroll
  for (int r=0;r<4;r++){
    mx[r] = fmaxf(red[w0*8+r],   red[w1*8+r]);
    cx[r] = fmaxf(red[w0*8+4+r], red[w1*8+4+r]);
  }

  // ---- exp in registers + row sums
  float s[4] = {0.f,0.f,0.f,0.f};
  #pragma unroll
  for (int jj=0;jj<7;jj++){
    bool v = (jj<6) || (jslot<8);
    #pragma unroll
    for (int r=0;r<4;r++){
      float e = v ? __expf(acc[r][jj]-mx[r]) : 0.f;
      acc[r][jj]=e;
      s[r]+=e;
    }
  }
  #pragma unroll
  for (int r=0;r<4;r++) s[r]=warpSum(s[r]);
  __syncthreads();
  if (lane==0){
    #pragma unroll
    for (int r=0;r<4;r++) red[w*8+r]=s[r];
  }
  __syncthreads();
  float inv[4], aq[4];
  #pragma unroll
  for (int r=0;r<4;r++){
    inv[r] = 1.0f/(red[w0*8+r]+red[w1*8+r]);
    aq[r]  = __expf(cx[r]-mx[r])*inv[r] + 1e-6f;
  }

  // ---- probs straight from registers (coalesced)
  #pragma unroll
  for (int r=0;r<4;r++){
    float* pr = g_probs + ((size_t)m*Nn + irow[r])*Nn;
    #pragma unroll
    for (int jj=0;jj<7;jj++){
      int j = jslot + (jj<<6);
      bool v = (jj<6) || (jslot<8);
      if (v) pr[j] = acc[r][jj]*inv[r];
    }
  }

  // ---- same-side sp sums
  float ss[4] = {0.f,0.f,0.f,0.f};
  #pragma unroll
  for (int jj=0;jj<7;jj++){
    int j = jslot + (jj<<6);
    bool v = (jj<6) || (jslot<8);
    if (v){
      #pragma unroll
      for (int r=0;r<4;r++){
        int jl = j - same[r];
        if (jl>=0 && jl<LF && j!=irow[r]) ss[r] += acc[r][jj]*inv[r] + 1e-6f;
      }
    }
  }
  #pragma unroll
  for (int r=0;r<4;r++) ss[r]=warpSum(ss[r]);
  __syncthreads();
  if (lane==0){
    #pragma unroll
    for (int r=0;r<4;r++) red[w*8+4+r]=ss[r];
  }
  __syncthreads();
  float rc[4];
  #pragma unroll
  for (int r=0;r<4;r++)
    rc[r] = aq[r] / (red[w0*8+4+r]+red[w1*8+4+r]);

  // ---- sort keys: key = w * rcp(-ln u); diag -> 0
  #pragma unroll
  for (int r=0;r<4;r++){
    unsigned* sr = g_scores + (size_t)m*WROW + (size_t)irow[r]*LF;
    #pragma unroll
    for (int jj=0;jj<7;jj++){
      int j = jslot + (jj<<6);
      bool v = (jj<6) || (jslot<8);
      if (!v) continue;
      int jl = j - same[r];
      if (jl>=0 && jl<LF){
        unsigned key = 0u;
        if (j != irow[r]){
          float wv = (acc[r][jj]*inv[r] + 1e-6f)*rc[r];
          unsigned gi = (unsigned)(m*WROW + irow[r]*LF + jl);
          key = __float_as_uint(__fdividef(wv, neglogu_at(gi)));
        }
        sr[jl] = key;
      }
    }
  }
}

// ----------------------------------------------------------------------------
// Fused select+mask per m: 512 threads, writes BIT-PACKED mask words.
// ----------------------------------------------------------------------------
#define SELT 512
#define NWARP 16
#define REGION 4832   // multiple of 32; 15*4832 + 4352 = 76832

__global__ void __launch_bounds__(SELT) selmask_kernel(){
  int m = blockIdx.x, tid = threadIdx.x;
  const unsigned* row = g_scores + (size_t)m*WROW;
  unsigned* mwords = g_maskbits + (size_t)m*NWORD;
  __shared__ unsigned hist[256];
  __shared__ unsigned s_prefix;
  __shared__ int s_krem;
  __shared__ int weq[NWARP];

  unsigned prefix = 0; int krem = KSEL;
  for (int pass=0; pass<4; pass++){
    int shift = 24 - 8*pass;
    unsigned hm = pass ? (0xFFFFFFFFu << (shift+8)) : 0u;
    if (tid < 256) hist[tid] = 0;
    __syncthreads();
    for (int idx=tid; idx<WROW; idx+=SELT){
      unsigned u = row[idx];
      if ((u & hm) == prefix) atomicAdd(&hist[(u>>shift)&0xFFu], 1u);
    }
    __syncthreads();
    if (tid==0){
      int cum = 0, b = 255;
      for (; b>=0; b--){ cum += (int)hist[b]; if (cum >= krem) break; }
      int above = cum - (int)hist[b];
      s_prefix = prefix | ((unsigned)b << shift);
      s_krem = krem - above;
    }
    __syncthreads();
    prefix = s_prefix; krem = s_krem;
    __syncthreads();
  }
  const unsigned T = prefix;
  const int need = krem;

  int lane = tid & 31, w = tid >> 5;
  int lo = w*REGION, hi = min(lo + REGION, WROW);

  int ec = 0;
  for (int idx = lo + lane; idx < hi; idx += 32)
    ec += (row[idx] == T);
  #pragma unroll
  for (int o=16;o>0;o>>=1) ec += __shfl_xor_sync(0xffffffffu, ec, o);
  if (lane==0) weq[w] = ec;
  __syncthreads();
  int base = 0;
  for (int ww=0; ww<w; ww++) base += weq[ww];

  int run = base;
  for (int idx0 = lo; idx0 < hi; idx0 += 32){
    int idx = idx0 + lane;
    unsigned u = row[idx];
    bool eq = (u == T);
    unsigned bal = __ballot_sync(0xffffffffu, eq);
    int rank = run + __popc(bal & ((1u<<lane)-1u));
    bool sel = (u > T) || (eq && rank < need);
    unsigned word = __ballot_sync(0xffffffffu, sel);
    if (lane==0) mwords[idx0 >> 5] = word;
    run += __popc(bal);
  }
}

// ----------------------------------------------------------------------------
// attn kernel v5: block = (m, 8 rows), 128 threads, warp = 2 rows.
// V line loaded once serves both rows; 4 independent FMA chains.
// ----------------------------------------------------------------------------
__global__ void __launch_bounds__(128, 8) attn_kernel(){
  int blk = blockIdx.x;
  int m = blk / 49, it = blk % 49;
  int lane = threadIdx.x & 31, w = threadIdx.x >> 5;   // w in 0..3
  int i0 = it*8;
  __shared__ float l[8][Nn];

  const unsigned* mb = g_maskbits + (size_t)m*NWORD;

  #pragma unroll 1
  for (int rr=0; rr<2; rr++){
    int i = i0 + w*2 + rr;
    int same = (i >= LF) ? LF : 0;
    int base_bit = i*LF;
    int w0 = base_bit >> 5, off = base_bit & 31;
    unsigned mw[8];
    #pragma unroll
    for (int k=0;k<8;k++) mw[k] = __ldg(mb + w0 + k);  // +8 pad makes this safe

    const float* pr = g_probs + ((size_t)m*Nn + i)*Nn;
    float p[13];
    float dsum = 0.f;
    #pragma unroll
    for (int k=0;k<13;k++){
      int j = lane + 32*k;
      float v = (j < Nn) ? __ldg(pr + j) : 0.f;
      int jl = j - same;
      if (jl >= 0 && jl < LF){
        int s0 = off + 32*k - same;        // == off + jl - lane (warp-uniform)
        int wlo = s0 >> 5, sh = s0 & 31;
        unsigned f = __funnelshift_r(mw[wlo], mw[wlo+1], sh);
        if ((f >> lane) & 1u) v = 0.f;
      }
      p[k] = v;
      dsum += v;
    }
    float inv = 1.0f/warpSum(dsum);
    #pragma unroll
    for (int k=0;k<13;k++){
      int j = lane + 32*k;
      if (j < Nn) l[w*2+rr][j] = p[k]*inv;
    }
  }
  __syncwarp();

  const int r0 = w*2, r1 = r0+1;
  const float* vb = g_v + (size_t)m*Nn*HD + lane;
  const float* l0 = l[r0];
  const float* l1 = l[r1];
  float a00=0.f, a01=0.f, a10=0.f, a11=0.f;
  #pragma unroll 2
  for (int j=0; j<Nn; j+=2){
    float v0 = vb[(size_t)j*HD];
    float v1 = vb[(size_t)(j+1)*HD];
    a00 += l0[j]*v0;   a10 += l1[j]*v0;
    a01 += l0[j+1]*v1; a11 += l1[j+1]*v1;
  }
  float acc0 = a00 + a01;
  float acc1 = a10 + a11;

  int b = m >> 4, h = m & 15;
  g_o[((size_t)(b*Nn + (i0+r0)))*Cc + h*HD + lane] = acc0;
  g_o[((size_t)(b*Nn + (i0+r1)))*Cc + h*HD + lane] = acc1;
}

// ----------------------------------------------------------------------------
// Launch
// ----------------------------------------------------------------------------
extern "C" void kernel_launch(void* const* d_in, const int* in_sizes, int n_in,
                              void* d_out, int out_size){
  const float* x      = (const float*)d_in[0];
  const float* n1w    = (const float*)d_in[1];
  const float* n1b    = (const float*)d_in[2];
  const float* qkv_w  = (const float*)d_in[3];
  const float* qkv_b  = (const float*)d_in[4];
  const float* proj_w = (const float*)d_in[5];
  const float* proj_b = (const float*)d_in[6];
  const float* n2w    = (const float*)d_in[7];
  const float* n2b    = (const float*)d_in[8];
  const float* fc1_w  = (const float*)d_in[9];
  const float* fc1_b  = (const float*)d_in[10];
  const float* fc2_w  = (const float*)d_in[11];
  const float* fc2_b  = (const float*)d_in[12];
  float* out = (float*)d_out;

  float *p_h, *p_qkv, *p_o, *p_x1, *p_h2, *p_mlp;
  cudaGetSymbolAddress((void**)&p_h,   g_h);
  cudaGetSymbolAddress((void**)&p_qkv, g_qkv);
  cudaGetSymbolAddress((void**)&p_o,   g_o);
  cudaGetSymbolAddress((void**)&p_x1,  g_x1);
  cudaGetSymbolAddress((void**)&p_h2,  g_h2);
  cudaGetSymbolAddress((void**)&p_mlp, g_mlp);

  // allow >48KB dynamic smem (idempotent)
  cudaFuncSetAttribute(score_kernel,
                       cudaFuncAttributeMaxDynamicSharedMemorySize, SC_SMEM);
  cudaFuncSetAttribute(gemm_tf32,
                       cudaFuncAttributeMaxDynamicSharedMemorySize, GEMM_SMEM);

  // 1) LN1
  ln_kernel<<<ROWS, 256>>>(x, n1w, n1b, p_h);
  // 2) QKV GEMM
  gemm_tf32<<<dim3(3*Cc/128, ROWS/128), 256, GEMM_SMEM>>>(p_h, qkv_w, qkv_b, nullptr, p_qkv,
                                               ROWS, 3*Cc, Cc, 0);
  // 3) reorder to per-head Q/K/V
  reorder_qkv<<<(ROWS*3*Cc + 255)/256, 256>>>();
  // 4) QK (smem-staged, swizzled) + probs + sort keys (4 rows/thread)
  score_kernel<<<Mm*49, 128, SC_SMEM>>>();
  // 5) fused top-k threshold + bit-packed mask
  selmask_kernel<<<Mm, SELT>>>();
  // 6) renormalize masked probs + AV (2 rows per warp)
  attn_kernel<<<Mm*49, 128>>>();
  // 7) proj + residual(x)
  gemm_tf32<<<dim3(Cc/128, ROWS/128), 256, GEMM_SMEM>>>(p_o, proj_w, proj_b, x, p_x1,
                                             ROWS, Cc, Cc, 0);
  // 8) LN2
  ln_kernel<<<ROWS, 256>>>(p_x1, n2w, n2b, p_h2);
  // 9) fc1 + exact gelu
  gemm_tf32<<<dim3(MLPH/128, ROWS/128), 256, GEMM_SMEM>>>(p_h2, fc1_w, fc1_b, nullptr, p_mlp,
                                               ROWS, MLPH, Cc, 1);
  // 10) fc2 + residual(x1) -> out
  gemm_tf32<<<dim3(Cc/128, ROWS/128), 256, GEMM_SMEM>>>(p_mlp, fc2_w, fc2_b, p_x1, out,
                                             ROWS, Cc, MLPH, 0);
}

// round 14
// speedup vs baseline: 1.0798x; 1.0798x over previous
#include <cuda_runtime.h>
#include <cuda_bf16.h>
#include <math.h>

// ----------------------------------------------------------------------------
// Problem constants
// ----------------------------------------------------------------------------
#define Bz   16
#define Nn   392
#define Cc   512
#define Hh   16
#define HD   32
#define Mm   (Bz*Hh)          // 256
#define LF   196              // Nn/2
#define MLPH 2048
#define ROWS (Bz*Nn)          // 6272
#define WROW (Nn*LF)          // 76832  scores per m
#define KSEL 7448             // int(0.1*195)*392
#define NWORD 2401            // WROW/32 mask words per m
#define NEGBIG (-3.4e38f)

// score kernel smem layout
#define KS_BYTES (Nn*8*16)            // 50176: K tile, float4 chunks, swizzled
#define QS_BYTES (8*32*4)             // 1024 : 8 scaled q rows
#define RED_BYTES 128                 // 4 rg x 2 wh x 4 floats
#define SC_SMEM (KS_BYTES + QS_BYTES + RED_BYTES)

// ----------------------------------------------------------------------------
// Scratch (static device globals; no allocation at runtime)
// ----------------------------------------------------------------------------
__device__ float g_h   [ROWS*Cc];
__device__ float g_qkv [ROWS*3*Cc];
__device__ float g_q   [Mm*Nn*HD];
__device__ float g_k   [Mm*Nn*HD];
__device__ float g_v   [Mm*Nn*HD];
__device__ float g_probs[(size_t)Mm*Nn*Nn];     // unmasked softmax probs
__device__ unsigned g_scores[(size_t)Mm*WROW];  // positive-float sort keys
__device__ unsigned g_maskbits[(size_t)Mm*NWORD + 8];
__device__ float g_o   [ROWS*Cc];
__device__ float g_x1  [ROWS*Cc];
__device__ float g_h2  [ROWS*Cc];
__device__ float g_mlp [ROWS*MLPH];

// ----------------------------------------------------------------------------
// Reductions
// ----------------------------------------------------------------------------
__device__ __forceinline__ float warpMax(float v){
  #pragma unroll
  for (int o=16;o>0;o>>=1) v = fmaxf(v, __shfl_xor_sync(0xffffffffu, v, o));
  return v;
}
__device__ __forceinline__ float warpSum(float v){
  #pragma unroll
  for (int o=16;o>0;o>>=1) v += __shfl_xor_sync(0xffffffffu, v, o);
  return v;
}
template<int NW>
__device__ __forceinline__ float blockSum(float v, float* sw){
  int lane = threadIdx.x & 31, w = threadIdx.x >> 5;
  v = warpSum(v);
  if (lane==0) sw[w] = v;
  __syncthreads();
  float r = 0.f;
  #pragma unroll
  for (int i=0;i<NW;i++) r += sw[i];
  __syncthreads();
  return r;
}

// ----------------------------------------------------------------------------
// JAX threefry2x32, key (0,42), partitionable 32-bit path
// ----------------------------------------------------------------------------
__device__ __forceinline__ unsigned rotl32(unsigned x, int r){ return (x<<r)|(x>>(32-r)); }
__device__ __forceinline__ unsigned threefry_bits(unsigned idx){
  const unsigned k0 = 0u, k1 = 42u;
  const unsigned k2 = k0 ^ k1 ^ 0x1BD11BDAu;
  unsigned x0 = 0u + k0;
  unsigned x1 = idx + k1;
#define TFR(r) { x0 += x1; x1 = rotl32(x1,(r)); x1 ^= x0; }
  TFR(13) TFR(15) TFR(26) TFR(6)
  x0 += k1; x1 += k2 + 1u;
  TFR(17) TFR(29) TFR(16) TFR(24)
  x0 += k2; x1 += k0 + 2u;
  TFR(13) TFR(15) TFR(26) TFR(6)
  x0 += k0; x1 += k1 + 3u;
  TFR(17) TFR(29) TFR(16) TFR(24)
  x0 += k1; x1 += k2 + 4u;
  TFR(13) TFR(15) TFR(26) TFR(6)
  x0 += k2; x1 += k0 + 5u;
#undef TFR
  return x0 ^ x1;
}
// returns -ln(u) for the gumbel draw at flat index idx  (1 MUFU log)
__device__ __forceinline__ float neglogu_at(unsigned idx){
  unsigned bits = threefry_bits(idx);
  float f = __uint_as_float((bits >> 9) | 0x3f800000u) - 1.0f;
  const float tiny = 1.17549435e-38f;
  float u = fmaxf(tiny, f + tiny);
  return -__logf(u);
}

// ----------------------------------------------------------------------------
// LayerNorm (one block per row, 256 threads, C=512)
// ----------------------------------------------------------------------------
__global__ void __launch_bounds__(256) ln_kernel(const float* __restrict__ x,
                                                 const float* __restrict__ w,
                                                 const float* __restrict__ bias,
                                                 float* __restrict__ out){
  int row = blockIdx.x, t = threadIdx.x;
  const float* xr = x + (size_t)row*Cc;
  __shared__ float sw[8];
  float a = xr[t], b = xr[t+256];
  float s = blockSum<8>(a+b, sw);
  float mu = s * (1.0f/512.0f);
  float da = a-mu, db = b-mu;
  float v = blockSum<8>(da*da + db*db, sw);
  float rstd = rsqrtf(v*(1.0f/512.0f) + 1e-5f);
  out[(size_t)row*Cc + t]     = da*rstd*w[t]     + bias[t];
  out[(size_t)row*Cc + t+256] = db*rstd*w[t+256] + bias[t+256];
}

// ----------------------------------------------------------------------------
// tf32 tensor-core GEMM: 128x128 tile, BK=16, 256 threads, mma.m16n8k8.tf32,
// cp.async 3-stage pipeline (dynamic smem). Raw fp32 bits fed to tf32 mma.
// act: 0 = bias(+res), 1 = bias+gelu
// ----------------------------------------------------------------------------
__device__ __forceinline__ void cp16(float* dst, const float* src){
  unsigned d = (unsigned)__cvta_generic_to_shared(dst);
  asm volatile("cp.async.ca.shared.global [%0], [%1], 16;\n" :: "r"(d), "l"(src));
}
__device__ __forceinline__ void mma_tf32(float* c, const unsigned* a, const unsigned* b){
  asm volatile(
    "mma.sync.aligned.m16n8k8.row.col.f32.tf32.tf32.f32 "
    "{%0,%1,%2,%3},{%4,%5,%6,%7},{%8,%9},{%0,%1,%2,%3};\n"
    : "+f"(c[0]),"+f"(c[1]),"+f"(c[2]),"+f"(c[3])
    : "r"(a[0]),"r"(a[1]),"r"(a[2]),"r"(a[3]),"r"(b[0]),"r"(b[1]));
}

#define APAD 20
#define BPAD 136
#define AS_STRIDE (128*APAD)          // floats per A stage
#define BS_STRIDE (16*BPAD)           // floats per B stage
#define GEMM_SMEM ((3*AS_STRIDE + 3*BS_STRIDE)*4)   // 56832 bytes

__global__ void __launch_bounds__(256, 2) gemm_tf32(const float* __restrict__ A,
                                                 const float* __restrict__ Bw,
                                                 const float* __restrict__ bias,
                                                 const float* __restrict__ res,
                                                 float* __restrict__ C,
                                                 int M, int N, int K, int act){
  extern __shared__ float gsm[];
  float* Asb = gsm;
  float* Bsb = gsm + 3*AS_STRIDE;
  const int tid = threadIdx.x;
  const int lane = tid & 31, wid = tid >> 5;
  const int wm = wid >> 2, wn = wid & 3;       // 2 x 4 warp grid
  const int bm = blockIdx.y*128, bn = blockIdx.x*128;

  float acc[16][4];
  #pragma unroll
  for (int i=0;i<16;i++){ acc[i][0]=0.f; acc[i][1]=0.f; acc[i][2]=0.f; acc[i][3]=0.f; }

  const int nT = K >> 4;

  auto load_stage = [&](int t, int buf){
    float* As = Asb + buf*AS_STRIDE;
    float* Bs = Bsb + buf*BS_STRIDE;
    int k0 = t << 4;
    #pragma unroll
    for (int r=0;r<2;r++){
      int i = tid + 256*r;
      int arow = i >> 2, ac = (i & 3) << 2;
      cp16(&As[arow*APAD + ac], A + (size_t)(bm+arow)*K + k0 + ac);
      int brow = i >> 5, bc = (i & 31) << 2;
      cp16(&Bs[brow*BPAD + bc], Bw + (size_t)(k0+brow)*N + bn + bc);
    }
    asm volatile("cp.async.commit_group;\n");
  };

  load_stage(0, 0);
  load_stage(1, 1);
  int cbuf = 0;   // compute buffer = t%3
  int lbuf = 2;   // load buffer   = (t+2)%3
  for (int t=0; t<nT; t++){
    if (t+2 < nT) load_stage(t+2, lbuf);
    if (t+2 < nT)      asm volatile("cp.async.wait_group 2;\n");
    else if (t+1 < nT) asm volatile("cp.async.wait_group 1;\n");
    else               asm volatile("cp.async.wait_group 0;\n");
    __syncthreads();
    const unsigned* as = (const unsigned*)(Asb + cbuf*AS_STRIDE);
    const unsigned* bs = (const unsigned*)(Bsb + cbuf*BS_STRIDE);
    #pragma unroll
    for (int ks=0; ks<16; ks+=8){
      unsigned a[4][4], b[4][2];
      #pragma unroll
      for (int mt=0;mt<4;mt++){
        int r0 = wm*64 + mt*16 + (lane>>2);
        int cc = ks + (lane&3);
        a[mt][0] = as[r0*APAD + cc];
        a[mt][1] = as[(r0+8)*APAD + cc];
        a[mt][2] = as[r0*APAD + cc + 4];
        a[mt][3] = as[(r0+8)*APAD + cc + 4];
      }
      #pragma unroll
      for (int nt=0;nt<4;nt++){
        int cn = wn*32 + nt*8 + (lane>>2);
        b[nt][0] = bs[(ks + (lane&3))*BPAD + cn];
        b[nt][1] = bs[(ks + 4 + (lane&3))*BPAD + cn];
      }
      #pragma unroll
      for (int mt=0;mt<4;mt++)
        #pragma unroll
        for (int nt=0;nt<4;nt++)
          mma_tf32(acc[mt*4+nt], a[mt], b[nt]);
    }
    __syncthreads();
    if (++cbuf == 3) cbuf = 0;
    if (++lbuf == 3) lbuf = 0;
  }

  #pragma unroll
  for (int mt=0;mt<4;mt++){
    #pragma unroll
    for (int nt=0;nt<4;nt++){
      float* c = acc[mt*4+nt];
      int gm = bm + wm*64 + mt*16 + (lane>>2);
      int gn = bn + wn*32 + nt*8 + ((lane&3)<<1);
      float b0 = bias[gn], b1 = bias[gn+1];
      #pragma unroll
      for (int hrow=0; hrow<2; hrow++){
        int gr = gm + hrow*8;
        float v0 = c[hrow*2+0] + b0;
        float v1 = c[hrow*2+1] + b1;
        if (act==1){
          v0 = 0.5f*v0*(1.0f + erff(v0*0.70710678118654752440f));
          v1 = 0.5f*v1*(1.0f + erff(v1*0.70710678118654752440f));
        }
        if (res){
          v0 += res[(size_t)gr*N + gn];
          v1 += res[(size_t)gr*N + gn+1];
        }
        C[(size_t)gr*N + gn]   = v0;
        C[(size_t)gr*N + gn+1] = v1;
      }
    }
  }
}

// ----------------------------------------------------------------------------
// QKV reorder: [row=b*392+i][3*512] -> Q/K/V [m=b*16+h][i][d]
// ----------------------------------------------------------------------------
__global__ void reorder_qkv(){
  int idx = blockIdx.x*blockDim.x + threadIdx.x;
  if (idx >= ROWS*3*Cc) return;
  int r = idx / (3*Cc), c = idx % (3*Cc);
  int which = c >> 9;
  int cc = c & 511;
  int h = cc >> 5, d = cc & 31;
  int b = r / Nn, i = r % Nn;
  float v = g_qkv[idx];
  size_t dst = ((size_t)((b*Hh+h)*Nn + i))*HD + d;
  if (which==0) g_q[dst]=v; else if (which==1) g_k[dst]=v; else g_v[dst]=v;
}

// ----------------------------------------------------------------------------
// score kernel v4 (measured 311us): block = (m, 8 query rows), 256 threads.
//  - K tile (392x32 f32 = 50KB) staged once in smem, XOR-swizzled chunks.
//  - 64 j-slots x 4 row-groups (2 rows/thread); logits stay in registers;
//    stats via 2-warp reductions through a tiny smem pad.
// ----------------------------------------------------------------------------
__global__ void __launch_bounds__(256) score_kernel(){
  extern __shared__ char sraw[];
  float4* ks  = (float4*)sraw;
  float*  qs  = (float*)(sraw + KS_BYTES);
  float*  red = (float*)(sraw + KS_BYTES + QS_BYTES);   // [4 rg][2 wh][4]

  int blk = blockIdx.x;
  int m = blk / 49, it = blk % 49;
  int i0 = it*8;
  int tid = threadIdx.x, lane = tid & 31;

  // stage q rows (scale folded in)
  {
    int i = tid >> 5, d = tid & 31;
    qs[i*32 + d] = g_q[((size_t)m*Nn + i0 + i)*HD + d] * 0.17677669529663687f;
  }
  // stage K, coalesced read, swizzled store
  const float4* kg = (const float4*)(g_k + (size_t)m*Nn*HD);
  #pragma unroll 1
  for (int c = tid; c < Nn*8; c += 256){
    int j = c >> 3, ch = c & 7;
    ks[(j<<3) | (ch ^ (j & 7))] = kg[c];
  }
  __syncthreads();

  const int rg = tid >> 6;           // 0..3  (row group: rows 2rg, 2rg+1)
  const int jslot = tid & 63;        // 0..63
  const int wh = (tid >> 5) & 1;     // warp half within row group
  const int sw = jslot & 7;
  const int r0 = rg*2, r1 = r0+1;

  // ---- QK dot: 14 register accumulators
  float a0[7], a1[7];
  #pragma unroll
  for (int jj=0;jj<7;jj++){ a0[jj]=0.f; a1[jj]=0.f; }

  #pragma unroll
  for (int t=0;t<8;t++){
    float4 qa = *(const float4*)&qs[r0*32 + t*4];
    float4 qb = *(const float4*)&qs[r1*32 + t*4];
    #pragma unroll
    for (int jj=0;jj<7;jj++){
      int j = jslot + (jj<<6);
      int jbase = (jj<6 || jslot<8) ? j : jslot;    // clamp invalid tail
      float4 kv = ks[(jbase<<3) | (t ^ sw)];
      a0[jj] += kv.x*qa.x + kv.y*qa.y + kv.z*qa.z + kv.w*qa.w;
      a1[jj] += kv.x*qb.x + kv.y*qb.y + kv.z*qb.z + kv.w*qb.w;
    }
  }

  const int ia = i0 + r0, ib = i0 + r1;
  const int sameA = (ia>=LF)?LF:0, sameB = (ib>=LF)?LF:0;

  // ---- round 1: row max + cross-side max
  float lm0=NEGBIG, lm1=NEGBIG, cm0=NEGBIG, cm1=NEGBIG;
  #pragma unroll
  for (int jj=0;jj<7;jj++){
    int j = jslot + (jj<<6);
    bool v = (jj<6) || (jslot<8);
    if (v){
      lm0 = fmaxf(lm0, a0[jj]);
      lm1 = fmaxf(lm1, a1[jj]);
      bool crA = sameA ? (j<LF) : (j>=LF);
      bool crB = sameB ? (j<LF) : (j>=LF);
      if (crA) cm0 = fmaxf(cm0, a0[jj]);
      if (crB) cm1 = fmaxf(cm1, a1[jj]);
    }
  }
  lm0=warpMax(lm0); lm1=warpMax(lm1); cm0=warpMax(cm0); cm1=warpMax(cm1);
  if (lane==0){
    float* rr = red + (rg*2+wh)*4;
    rr[0]=lm0; rr[1]=lm1; rr[2]=cm0; rr[3]=cm1;
  }
  __syncthreads();
  const float* rA = red + (rg*2+0)*4;
  const float* rB = red + (rg*2+1)*4;
  float mx0 = fmaxf(rA[0], rB[0]);
  float mx1 = fmaxf(rA[1], rB[1]);
  float cx0 = fmaxf(rA[2], rB[2]);
  float cx1 = fmaxf(rA[3], rB[3]);

  // ---- exp in registers + row sums
  float s0=0.f, s1=0.f;
  #pragma unroll
  for (int jj=0;jj<7;jj++){
    bool v = (jj<6) || (jslot<8);
    float e0 = v ? __expf(a0[jj]-mx0) : 0.f;
    float e1 = v ? __expf(a1[jj]-mx1) : 0.f;
    a0[jj]=e0; a1[jj]=e1;
    s0+=e0; s1+=e1;
  }
  s0=warpSum(s0); s1=warpSum(s1);
  __syncthreads();
  if (lane==0){ float* rr = red + (rg*2+wh)*4; rr[0]=s0; rr[1]=s1; }
  __syncthreads();
  float inv0 = 1.0f/(rA[0]+rB[0]);
  float inv1 = 1.0f/(rA[1]+rB[1]);
  float aq0 = __expf(cx0-mx0)*inv0 + 1e-6f;
  float aq1 = __expf(cx1-mx1)*inv1 + 1e-6f;

  // ---- probs straight from registers (coalesced)
  float* pr0 = g_probs + ((size_t)m*Nn + ia)*Nn;
  float* pr1 = g_probs + ((size_t)m*Nn + ib)*Nn;
  #pragma unroll
  for (int jj=0;jj<7;jj++){
    int j = jslot + (jj<<6);
    bool v = (jj<6) || (jslot<8);
    if (v){ pr0[j] = a0[jj]*inv0; pr1[j] = a1[jj]*inv1; }
  }

  // ---- same-side sp sums
  float ss0=0.f, ss1=0.f;
  #pragma unroll
  for (int jj=0;jj<7;jj++){
    int j = jslot + (jj<<6);
    bool v = (jj<6) || (jslot<8);
    if (v){
      int jl0 = j - sameA;
      if (jl0>=0 && jl0<LF && j!=ia) ss0 += a0[jj]*inv0 + 1e-6f;
      int jl1 = j - sameB;
      if (jl1>=0 && jl1<LF && j!=ib) ss1 += a1[jj]*inv1 + 1e-6f;
    }
  }
  ss0=warpSum(ss0); ss1=warpSum(ss1);
  __syncthreads();
  if (lane==0){ float* rr = red + (rg*2+wh)*4; rr[2]=ss0; rr[3]=ss1; }
  __syncthreads();
  float rc0 = aq0 / (rA[2]+rB[2]);
  float rc1 = aq1 / (rA[3]+rB[3]);

  // ---- sort keys: key = w * rcp(-ln u); diag -> 0
  unsigned* sr0 = g_scores + (size_t)m*WROW + (size_t)ia*LF;
  unsigned* sr1 = g_scores + (size_t)m*WROW + (size_t)ib*LF;
  #pragma unroll
  for (int jj=0;jj<7;jj++){
    int j = jslot + (jj<<6);
    bool v = (jj<6) || (jslot<8);
    if (!v) continue;
    int jl0 = j - sameA;
    if (jl0>=0 && jl0<LF){
      unsigned key = 0u;
      if (j != ia){
        float wv = (a0[jj]*inv0 + 1e-6f)*rc0;
        unsigned gi = (unsigned)(m*WROW + ia*LF + jl0);
        key = __float_as_uint(__fdividef(wv, neglogu_at(gi)));
      }
      sr0[jl0] = key;
    }
    int jl1 = j - sameB;
    if (jl1>=0 && jl1<LF){
      unsigned key = 0u;
      if (j != ib){
        float wv = (a1[jj]*inv1 + 1e-6f)*rc1;
        unsigned gi = (unsigned)(m*WROW + ib*LF + jl1);
        key = __float_as_uint(__fdividef(wv, neglogu_at(gi)));
      }
      sr1[jl1] = key;
    }
  }
}

// ----------------------------------------------------------------------------
// Fused select+mask per m: 512 threads, writes BIT-PACKED mask words.
// ----------------------------------------------------------------------------
#define SELT 512
#define NWARP 16
#define REGION 4832   // multiple of 32; 15*4832 + 4352 = 76832

__global__ void __launch_bounds__(SELT) selmask_kernel(){
  int m = blockIdx.x, tid = threadIdx.x;
  const unsigned* row = g_scores + (size_t)m*WROW;
  unsigned* mwords = g_maskbits + (size_t)m*NWORD;
  __shared__ unsigned hist[256];
  __shared__ unsigned s_prefix;
  __shared__ int s_krem;
  __shared__ int weq[NWARP];

  unsigned prefix = 0; int krem = KSEL;
  for (int pass=0; pass<4; pass++){
    int shift = 24 - 8*pass;
    unsigned hm = pass ? (0xFFFFFFFFu << (shift+8)) : 0u;
    if (tid < 256) hist[tid] = 0;
    __syncthreads();
    for (int idx=tid; idx<WROW; idx+=SELT){
      unsigned u = row[idx];
      if ((u & hm) == prefix) atomicAdd(&hist[(u>>shift)&0xFFu], 1u);
    }
    __syncthreads();
    if (tid==0){
      int cum = 0, b = 255;
      for (; b>=0; b--){ cum += (int)hist[b]; if (cum >= krem) break; }
      int above = cum - (int)hist[b];
      s_prefix = prefix | ((unsigned)b << shift);
      s_krem = krem - above;
    }
    __syncthreads();
    prefix = s_prefix; krem = s_krem;
    __syncthreads();
  }
  const unsigned T = prefix;
  const int need = krem;

  int lane = tid & 31, w = tid >> 5;
  int lo = w*REGION, hi = min(lo + REGION, WROW);

  int ec = 0;
  for (int idx = lo + lane; idx < hi; idx += 32)
    ec += (row[idx] == T);
  #pragma unroll
  for (int o=16;o>0;o>>=1) ec += __shfl_xor_sync(0xffffffffu, ec, o);
  if (lane==0) weq[w] = ec;
  __syncthreads();
  int base = 0;
  for (int ww=0; ww<w; ww++) base += weq[ww];

  int run = base;
  for (int idx0 = lo; idx0 < hi; idx0 += 32){
    int idx = idx0 + lane;
    unsigned u = row[idx];
    bool eq = (u == T);
    unsigned bal = __ballot_sync(0xffffffffu, eq);
    int rank = run + __popc(bal & ((1u<<lane)-1u));
    bool sel = (u > T) || (eq && rank < need);
    unsigned word = __ballot_sync(0xffffffffu, sel);
    if (lane==0) mwords[idx0 >> 5] = word;
    run += __popc(bal);
  }
}

// ----------------------------------------------------------------------------
// attn kernel v5: block = (m, 8 rows), 128 threads, warp = 2 rows.
// V line loaded once serves both rows; 4 independent FMA chains.
// ----------------------------------------------------------------------------
__global__ void __launch_bounds__(128, 8) attn_kernel(){
  int blk = blockIdx.x;
  int m = blk / 49, it = blk % 49;
  int lane = threadIdx.x & 31, w = threadIdx.x >> 5;   // w in 0..3
  int i0 = it*8;
  __shared__ float l[8][Nn];

  const unsigned* mb = g_maskbits + (size_t)m*NWORD;

  #pragma unroll 1
  for (int rr=0; rr<2; rr++){
    int i = i0 + w*2 + rr;
    int same = (i >= LF) ? LF : 0;
    int base_bit = i*LF;
    int w0 = base_bit >> 5, off = base_bit & 31;
    unsigned mw[8];
    #pragma unroll
    for (int k=0;k<8;k++) mw[k] = __ldg(mb + w0 + k);  // +8 pad makes this safe

    const float* pr = g_probs + ((size_t)m*Nn + i)*Nn;
    float p[13];
    float dsum = 0.f;
    #pragma unroll
    for (int k=0;k<13;k++){
      int j = lane + 32*k;
      float v = (j < Nn) ? __ldg(pr + j) : 0.f;
      int jl = j - same;
      if (jl >= 0 && jl < LF){
        int s0 = off + 32*k - same;        // == off + jl - lane (warp-uniform)
        int wlo = s0 >> 5, sh = s0 & 31;
        unsigned f = __funnelshift_r(mw[wlo], mw[wlo+1], sh);
        if ((f >> lane) & 1u) v = 0.f;
      }
      p[k] = v;
      dsum += v;
    }
    float inv = 1.0f/warpSum(dsum);
    #pragma unroll
    for (int k=0;k<13;k++){
      int j = lane + 32*k;
      if (j < Nn) l[w*2+rr][j] = p[k]*inv;
    }
  }
  __syncwarp();

  const int r0 = w*2, r1 = r0+1;
  const float* vb = g_v + (size_t)m*Nn*HD + lane;
  const float* l0 = l[r0];
  const float* l1 = l[r1];
  float a00=0.f, a01=0.f, a10=0.f, a11=0.f;
  #pragma unroll 2
  for (int j=0; j<Nn; j+=2){
    float v0 = vb[(size_t)j*HD];
    float v1 = vb[(size_t)(j+1)*HD];
    a00 += l0[j]*v0;   a10 += l1[j]*v0;
    a01 += l0[j+1]*v1; a11 += l1[j+1]*v1;
  }
  float acc0 = a00 + a01;
  float acc1 = a10 + a11;

  int b = m >> 4, h = m & 15;
  g_o[((size_t)(b*Nn + (i0+r0)))*Cc + h*HD + lane] = acc0;
  g_o[((size_t)(b*Nn + (i0+r1)))*Cc + h*HD + lane] = acc1;
}

// ----------------------------------------------------------------------------
// Launch
// ----------------------------------------------------------------------------
extern "C" void kernel_launch(void* const* d_in, const int* in_sizes, int n_in,
                              void* d_out, int out_size){
  const float* x      = (const float*)d_in[0];
  const float* n1w    = (const float*)d_in[1];
  const float* n1b    = (const float*)d_in[2];
  const float* qkv_w  = (const float*)d_in[3];
  const float* qkv_b  = (const float*)d_in[4];
  const float* proj_w = (const float*)d_in[5];
  const float* proj_b = (const float*)d_in[6];
  const float* n2w    = (const float*)d_in[7];
  const float* n2b    = (const float*)d_in[8];
  const float* fc1_w  = (const float*)d_in[9];
  const float* fc1_b  = (const float*)d_in[10];
  const float* fc2_w  = (const float*)d_in[11];
  const float* fc2_b  = (const float*)d_in[12];
  float* out = (float*)d_out;

  float *p_h, *p_qkv, *p_o, *p_x1, *p_h2, *p_mlp;
  cudaGetSymbolAddress((void**)&p_h,   g_h);
  cudaGetSymbolAddress((void**)&p_qkv, g_qkv);
  cudaGetSymbolAddress((void**)&p_o,   g_o);
  cudaGetSymbolAddress((void**)&p_x1,  g_x1);
  cudaGetSymbolAddress((void**)&p_h2,  g_h2);
  cudaGetSymbolAddress((void**)&p_mlp, g_mlp);

  // allow >48KB dynamic smem (idempotent)
  cudaFuncSetAttribute(score_kernel,
                       cudaFuncAttributeMaxDynamicSharedMemorySize, SC_SMEM);
  cudaFuncSetAttribute(gemm_tf32,
                       cudaFuncAttributeMaxDynamicSharedMemorySize, GEMM_SMEM);

  // 1) LN1
  ln_kernel<<<ROWS, 256>>>(x, n1w, n1b, p_h);
  // 2) QKV GEMM
  gemm_tf32<<<dim3(3*Cc/128, ROWS/128), 256, GEMM_SMEM>>>(p_h, qkv_w, qkv_b, nullptr, p_qkv,
                                               ROWS, 3*Cc, Cc, 0);
  // 3) reorder to per-head Q/K/V
  reorder_qkv<<<(ROWS*3*Cc + 255)/256, 256>>>();
  // 4) QK (smem-staged, swizzled) + probs + sort keys
  score_kernel<<<Mm*49, 256, SC_SMEM>>>();
  // 5) fused top-k threshold + bit-packed mask
  selmask_kernel<<<Mm, SELT>>>();
  // 6) renormalize masked probs + AV (2 rows per warp)
  attn_kernel<<<Mm*49, 128>>>();
  // 7) proj + residual(x)
  gemm_tf32<<<dim3(Cc/128, ROWS/128), 256, GEMM_SMEM>>>(p_o, proj_w, proj_b, x, p_x1,
                                             ROWS, Cc, Cc, 0);
  // 8) LN2
  ln_kernel<<<ROWS, 256>>>(p_x1, n2w, n2b, p_h2);
  // 9) fc1 + exact gelu
  gemm_tf32<<<dim3(MLPH/128, ROWS/128), 256, GEMM_SMEM>>>(p_h2, fc1_w, fc1_b, nullptr, p_mlp,
                                               ROWS, MLPH, Cc, 1);
  // 10) fc2 + residual(x1) -> out
  gemm_tf32<<<dim3(Cc/128, ROWS/128), 256, GEMM_SMEM>>>(p_mlp, fc2_w, fc2_b, p_x1, out,
                                             ROWS, Cc, MLPH, 0);
}

// round 15
// speedup vs baseline: 1.1173x; 1.0347x over previous
#include <cuda_runtime.h>
#include <cuda_bf16.h>
#include <math.h>

// ----------------------------------------------------------------------------
// Problem constants
// ----------------------------------------------------------------------------
#define Bz   16
#define Nn   392
#define Cc   512
#define Hh   16
#define HD   32
#define Mm   (Bz*Hh)          // 256
#define LF   196              // Nn/2
#define MLPH 2048
#define ROWS (Bz*Nn)          // 6272
#define WROW (Nn*LF)          // 76832  scores per m
#define KSEL 7448             // int(0.1*195)*392
#define NWORD 2401            // WROW/32 mask words per m
#define NEGBIG (-3.4e38f)

// score kernel smem layout
#define KS_BYTES (Nn*8*16)            // 50176: K tile, float4 chunks, swizzled
#define QS_BYTES (8*32*4)             // 1024 : 8 scaled q rows
#define RED_BYTES 128                 // 4 rg x 2 wh x 4 floats
#define SC_SMEM (KS_BYTES + QS_BYTES + RED_BYTES)

// ----------------------------------------------------------------------------
// Scratch (static device globals; no allocation at runtime)
// ----------------------------------------------------------------------------
__device__ float g_h   [ROWS*Cc];
__device__ float g_qkv [ROWS*3*Cc];
__device__ float g_q   [Mm*Nn*HD];
__device__ float g_k   [Mm*Nn*HD];
__device__ float g_v   [Mm*Nn*HD];
__device__ float g_probs[(size_t)Mm*Nn*Nn];     // unmasked softmax probs
__device__ unsigned g_scores[(size_t)Mm*WROW];  // positive-float sort keys
__device__ unsigned g_maskbits[(size_t)Mm*NWORD + 8];
__device__ float g_o   [ROWS*Cc];
__device__ float g_x1  [ROWS*Cc];
__device__ float g_h2  [ROWS*Cc];
__device__ float g_mlp [ROWS*MLPH];

// ----------------------------------------------------------------------------
// Reductions
// ----------------------------------------------------------------------------
__device__ __forceinline__ float warpMax(float v){
  #pragma unroll
  for (int o=16;o>0;o>>=1) v = fmaxf(v, __shfl_xor_sync(0xffffffffu, v, o));
  return v;
}
__device__ __forceinline__ float warpSum(float v){
  #pragma unroll
  for (int o=16;o>0;o>>=1) v += __shfl_xor_sync(0xffffffffu, v, o);
  return v;
}
template<int NW>
__device__ __forceinline__ float blockSum(float v, float* sw){
  int lane = threadIdx.x & 31, w = threadIdx.x >> 5;
  v = warpSum(v);
  if (lane==0) sw[w] = v;
  __syncthreads();
  float r = 0.f;
  #pragma unroll
  for (int i=0;i<NW;i++) r += sw[i];
  __syncthreads();
  return r;
}

// ----------------------------------------------------------------------------
// JAX threefry2x32, key (0,42), partitionable 32-bit path
// ----------------------------------------------------------------------------
__device__ __forceinline__ unsigned rotl32(unsigned x, int r){ return (x<<r)|(x>>(32-r)); }
__device__ __forceinline__ unsigned threefry_bits(unsigned idx){
  const unsigned k0 = 0u, k1 = 42u;
  const unsigned k2 = k0 ^ k1 ^ 0x1BD11BDAu;
  unsigned x0 = 0u + k0;
  unsigned x1 = idx + k1;
#define TFR(r) { x0 += x1; x1 = rotl32(x1,(r)); x1 ^= x0; }
  TFR(13) TFR(15) TFR(26) TFR(6)
  x0 += k1; x1 += k2 + 1u;
  TFR(17) TFR(29) TFR(16) TFR(24)
  x0 += k2; x1 += k0 + 2u;
  TFR(13) TFR(15) TFR(26) TFR(6)
  x0 += k0; x1 += k1 + 3u;
  TFR(17) TFR(29) TFR(16) TFR(24)
  x0 += k1; x1 += k2 + 4u;
  TFR(13) TFR(15) TFR(26) TFR(6)
  x0 += k2; x1 += k0 + 5u;
#undef TFR
  return x0 ^ x1;
}
// returns -ln(u) for the gumbel draw at flat index idx  (1 MUFU log)
__device__ __forceinline__ float neglogu_at(unsigned idx){
  unsigned bits = threefry_bits(idx);
  float f = __uint_as_float((bits >> 9) | 0x3f800000u) - 1.0f;
  const float tiny = 1.17549435e-38f;
  float u = fmaxf(tiny, f + tiny);
  return -__logf(u);
}

// ----------------------------------------------------------------------------
// LayerNorm (one block per row, 256 threads, C=512)
// ----------------------------------------------------------------------------
__global__ void __launch_bounds__(256) ln_kernel(const float* __restrict__ x,
                                                 const float* __restrict__ w,
                                                 const float* __restrict__ bias,
                                                 float* __restrict__ out){
  int row = blockIdx.x, t = threadIdx.x;
  const float* xr = x + (size_t)row*Cc;
  __shared__ float sw[8];
  float a = xr[t], b = xr[t+256];
  float s = blockSum<8>(a+b, sw);
  float mu = s * (1.0f/512.0f);
  float da = a-mu, db = b-mu;
  float v = blockSum<8>(da*da + db*db, sw);
  float rstd = rsqrtf(v*(1.0f/512.0f) + 1e-5f);
  out[(size_t)row*Cc + t]     = da*rstd*w[t]     + bias[t];
  out[(size_t)row*Cc + t+256] = db*rstd*w[t+256] + bias[t+256];
}

// ----------------------------------------------------------------------------
// tf32 tensor-core GEMM: 128x128 tile, BK=16, 256 threads, mma.m16n8k8.tf32,
// cp.async 4-stage ring, ONE __syncthreads per k-tile. Raw fp32 bits fed to
// tf32 mma. act: 0 = bias(+res), 1 = bias+gelu
// ----------------------------------------------------------------------------
__device__ __forceinline__ void cp16(float* dst, const float* src){
  unsigned d = (unsigned)__cvta_generic_to_shared(dst);
  asm volatile("cp.async.ca.shared.global [%0], [%1], 16;\n" :: "r"(d), "l"(src));
}
__device__ __forceinline__ void mma_tf32(float* c, const unsigned* a, const unsigned* b){
  asm volatile(
    "mma.sync.aligned.m16n8k8.row.col.f32.tf32.tf32.f32 "
    "{%0,%1,%2,%3},{%4,%5,%6,%7},{%8,%9},{%0,%1,%2,%3};\n"
    : "+f"(c[0]),"+f"(c[1]),"+f"(c[2]),"+f"(c[3])
    : "r"(a[0]),"r"(a[1]),"r"(a[2]),"r"(a[3]),"r"(b[0]),"r"(b[1]));
}

#define APAD 20
#define BPAD 136
#define AS_STRIDE (128*APAD)          // floats per A stage
#define BS_STRIDE (16*BPAD)           // floats per B stage
#define GEMM_SMEM ((4*AS_STRIDE + 4*BS_STRIDE)*4)   // 75776 bytes

__global__ void __launch_bounds__(256, 2) gemm_tf32(const float* __restrict__ A,
                                                 const float* __restrict__ Bw,
                                                 const float* __restrict__ bias,
                                                 const float* __restrict__ res,
                                                 float* __restrict__ C,
                                                 int M, int N, int K, int act){
  extern __shared__ float gsm[];
  float* Asb = gsm;
  float* Bsb = gsm + 4*AS_STRIDE;
  const int tid = threadIdx.x;
  const int lane = tid & 31, wid = tid >> 5;
  const int wm = wid >> 2, wn = wid & 3;       // 2 x 4 warp grid
  const int bm = blockIdx.y*128, bn = blockIdx.x*128;

  float acc[16][4];
  #pragma unroll
  for (int i=0;i<16;i++){ acc[i][0]=0.f; acc[i][1]=0.f; acc[i][2]=0.f; acc[i][3]=0.f; }

  const int nT = K >> 4;

  auto load_stage = [&](int t, int buf){
    float* As = Asb + buf*AS_STRIDE;
    float* Bs = Bsb + buf*BS_STRIDE;
    int k0 = t << 4;
    #pragma unroll
    for (int r=0;r<2;r++){
      int i = tid + 256*r;
      int arow = i >> 2, ac = (i & 3) << 2;
      cp16(&As[arow*APAD + ac], A + (size_t)(bm+arow)*K + k0 + ac);
      int brow = i >> 5, bc = (i & 31) << 2;
      cp16(&Bs[brow*BPAD + bc], Bw + (size_t)(k0+brow)*N + bn + bc);
    }
    asm volatile("cp.async.commit_group;\n");
  };

  // prologue: 3 stages in flight
  load_stage(0, 0);
  load_stage(1, 1);
  load_stage(2, 2);
  for (int t=0; t<nT; t++){
    // need group t complete; pending after wait = min(2, nT-1-t)
    if (t+2 < nT)      asm volatile("cp.async.wait_group 2;\n");
    else if (t+1 < nT) asm volatile("cp.async.wait_group 1;\n");
    else               asm volatile("cp.async.wait_group 0;\n");
    __syncthreads();   // single barrier per tile (4-stage ring makes it safe)
    const int cbuf = t & 3;
    const unsigned* as = (const unsigned*)(Asb + cbuf*AS_STRIDE);
    const unsigned* bs = (const unsigned*)(Bsb + cbuf*BS_STRIDE);
    #pragma unroll
    for (int ks=0; ks<16; ks+=8){
      unsigned a[4][4], b[4][2];
      #pragma unroll
      for (int mt=0;mt<4;mt++){
        int r0 = wm*64 + mt*16 + (lane>>2);
        int cc = ks + (lane&3);
        a[mt][0] = as[r0*APAD + cc];
        a[mt][1] = as[(r0+8)*APAD + cc];
        a[mt][2] = as[r0*APAD + cc + 4];
        a[mt][3] = as[(r0+8)*APAD + cc + 4];
      }
      #pragma unroll
      for (int nt=0;nt<4;nt++){
        int cn = wn*32 + nt*8 + (lane>>2);
        b[nt][0] = bs[(ks + (lane&3))*BPAD + cn];
        b[nt][1] = bs[(ks + 4 + (lane&3))*BPAD + cn];
      }
      #pragma unroll
      for (int mt=0;mt<4;mt++)
        #pragma unroll
        for (int nt=0;nt<4;nt++)
          mma_tf32(acc[mt*4+nt], a[mt], b[nt]);
    }
    // load next-next-next tile AFTER compute: target (t+3)&3 != t&3, and all
    // warps are at iteration t (single sync above), so no reader collision.
    if (t+3 < nT) load_stage(t+3, (t+3) & 3);
  }

  #pragma unroll
  for (int mt=0;mt<4;mt++){
    #pragma unroll
    for (int nt=0;nt<4;nt++){
      float* c = acc[mt*4+nt];
      int gm = bm + wm*64 + mt*16 + (lane>>2);
      int gn = bn + wn*32 + nt*8 + ((lane&3)<<1);
      float b0 = bias[gn], b1 = bias[gn+1];
      #pragma unroll
      for (int hrow=0; hrow<2; hrow++){
        int gr = gm + hrow*8;
        float v0 = c[hrow*2+0] + b0;
        float v1 = c[hrow*2+1] + b1;
        if (act==1){
          v0 = 0.5f*v0*(1.0f + erff(v0*0.70710678118654752440f));
          v1 = 0.5f*v1*(1.0f + erff(v1*0.70710678118654752440f));
        }
        if (res){
          v0 += res[(size_t)gr*N + gn];
          v1 += res[(size_t)gr*N + gn+1];
        }
        C[(size_t)gr*N + gn]   = v0;
        C[(size_t)gr*N + gn+1] = v1;
      }
    }
  }
}

// ----------------------------------------------------------------------------
// QKV reorder: [row=b*392+i][3*512] -> Q/K/V [m=b*16+h][i][d]
// ----------------------------------------------------------------------------
__global__ void reorder_qkv(){
  int idx = blockIdx.x*blockDim.x + threadIdx.x;
  if (idx >= ROWS*3*Cc) return;
  int r = idx / (3*Cc), c = idx % (3*Cc);
  int which = c >> 9;
  int cc = c & 511;
  int h = cc >> 5, d = cc & 31;
  int b = r / Nn, i = r % Nn;
  float v = g_qkv[idx];
  size_t dst = ((size_t)((b*Hh+h)*Nn + i))*HD + d;
  if (which==0) g_q[dst]=v; else if (which==1) g_k[dst]=v; else g_v[dst]=v;
}

// ----------------------------------------------------------------------------
// score kernel v4 (measured 313us): block = (m, 8 query rows), 256 threads.
//  - K tile (392x32 f32 = 50KB) staged once in smem, XOR-swizzled chunks.
//  - 64 j-slots x 4 row-groups (2 rows/thread); logits stay in registers;
//    stats via 2-warp reductions through a tiny smem pad.
// ----------------------------------------------------------------------------
__global__ void __launch_bounds__(256) score_kernel(){
  extern __shared__ char sraw[];
  float4* ks  = (float4*)sraw;
  float*  qs  = (float*)(sraw + KS_BYTES);
  float*  red = (float*)(sraw + KS_BYTES + QS_BYTES);   // [4 rg][2 wh][4]

  int blk = blockIdx.x;
  int m = blk / 49, it = blk % 49;
  int i0 = it*8;
  int tid = threadIdx.x, lane = tid & 31;

  // stage q rows (scale folded in)
  {
    int i = tid >> 5, d = tid & 31;
    qs[i*32 + d] = g_q[((size_t)m*Nn + i0 + i)*HD + d] * 0.17677669529663687f;
  }
  // stage K, coalesced read, swizzled store
  const float4* kg = (const float4*)(g_k + (size_t)m*Nn*HD);
  #pragma unroll 1
  for (int c = tid; c < Nn*8; c += 256){
    int j = c >> 3, ch = c & 7;
    ks[(j<<3) | (ch ^ (j & 7))] = kg[c];
  }
  __syncthreads();

  const int rg = tid >> 6;           // 0..3  (row group: rows 2rg, 2rg+1)
  const int jslot = tid & 63;        // 0..63
  const int wh = (tid >> 5) & 1;     // warp half within row group
  const int sw = jslot & 7;
  const int r0 = rg*2, r1 = r0+1;

  // ---- QK dot: 14 register accumulators
  float a0[7], a1[7];
  #pragma unroll
  for (int jj=0;jj<7;jj++){ a0[jj]=0.f; a1[jj]=0.f; }

  #pragma unroll
  for (int t=0;t<8;t++){
    float4 qa = *(const float4*)&qs[r0*32 + t*4];
    float4 qb = *(const float4*)&qs[r1*32 + t*4];
    #pragma unroll
    for (int jj=0;jj<7;jj++){
      int j = jslot + (jj<<6);
      int jbase = (jj<6 || jslot<8) ? j : jslot;    // clamp invalid tail
      float4 kv = ks[(jbase<<3) | (t ^ sw)];
      a0[jj] += kv.x*qa.x + kv.y*qa.y + kv.z*qa.z + kv.w*qa.w;
      a1[jj] += kv.x*qb.x + kv.y*qb.y + kv.z*qb.z + kv.w*qb.w;
    }
  }

  const int ia = i0 + r0, ib = i0 + r1;
  const int sameA = (ia>=LF)?LF:0, sameB = (ib>=LF)?LF:0;

  // ---- round 1: row max + cross-side max
  float lm0=NEGBIG, lm1=NEGBIG, cm0=NEGBIG, cm1=NEGBIG;
  #pragma unroll
  for (int jj=0;jj<7;jj++){
    int j = jslot + (jj<<6);
    bool v = (jj<6) || (jslot<8);
    if (v){
      lm0 = fmaxf(lm0, a0[jj]);
      lm1 = fmaxf(lm1, a1[jj]);
      bool crA = sameA ? (j<LF) : (j>=LF);
      bool crB = sameB ? (j<LF) : (j>=LF);
      if (crA) cm0 = fmaxf(cm0, a0[jj]);
      if (crB) cm1 = fmaxf(cm1, a1[jj]);
    }
  }
  lm0=warpMax(lm0); lm1=warpMax(lm1); cm0=warpMax(cm0); cm1=warpMax(cm1);
  if (lane==0){
    float* rr = red + (rg*2+wh)*4;
    rr[0]=lm0; rr[1]=lm1; rr[2]=cm0; rr[3]=cm1;
  }
  __syncthreads();
  const float* rA = red + (rg*2+0)*4;
  const float* rB = red + (rg*2+1)*4;
  float mx0 = fmaxf(rA[0], rB[0]);
  float mx1 = fmaxf(rA[1], rB[1]);
  float cx0 = fmaxf(rA[2], rB[2]);
  float cx1 = fmaxf(rA[3], rB[3]);

  // ---- exp in registers + row sums
  float s0=0.f, s1=0.f;
  #pragma unroll
  for (int jj=0;jj<7;jj++){
    bool v = (jj<6) || (jslot<8);
    float e0 = v ? __expf(a0[jj]-mx0) : 0.f;
    float e1 = v ? __expf(a1[jj]-mx1) : 0.f;
    a0[jj]=e0; a1[jj]=e1;
    s0+=e0; s1+=e1;
  }
  s0=warpSum(s0); s1=warpSum(s1);
  __syncthreads();
  if (lane==0){ float* rr = red + (rg*2+wh)*4; rr[0]=s0; rr[1]=s1; }
  __syncthreads();
  float inv0 = 1.0f/(rA[0]+rB[0]);
  float inv1 = 1.0f/(rA[1]+rB[1]);
  float aq0 = __expf(cx0-mx0)*inv0 + 1e-6f;
  float aq1 = __expf(cx1-mx1)*inv1 + 1e-6f;

  // ---- probs straight from registers (coalesced)
  float* pr0 = g_probs + ((size_t)m*Nn + ia)*Nn;
  float* pr1 = g_probs + ((size_t)m*Nn + ib)*Nn;
  #pragma unroll
  for (int jj=0;jj<7;jj++){
    int j = jslot + (jj<<6);
    bool v = (jj<6) || (jslot<8);
    if (v){ pr0[j] = a0[jj]*inv0; pr1[j] = a1[jj]*inv1; }
  }

  // ---- same-side sp sums
  float ss0=0.f, ss1=0.f;
  #pragma unroll
  for (int jj=0;jj<7;jj++){
    int j = jslot + (jj<<6);
    bool v = (jj<6) || (jslot<8);
    if (v){
      int jl0 = j - sameA;
      if (jl0>=0 && jl0<LF && j!=ia) ss0 += a0[jj]*inv0 + 1e-6f;
      int jl1 = j - sameB;
      if (jl1>=0 && jl1<LF && j!=ib) ss1 += a1[jj]*inv1 + 1e-6f;
    }
  }
  ss0=warpSum(ss0); ss1=warpSum(ss1);
  __syncthreads();
  if (lane==0){ float* rr = red + (rg*2+wh)*4; rr[2]=ss0; rr[3]=ss1; }
  __syncthreads();
  float rc0 = aq0 / (rA[2]+rB[2]);
  float rc1 = aq1 / (rA[3]+rB[3]);

  // ---- sort keys: key = w * rcp(-ln u); diag -> 0
  unsigned* sr0 = g_scores + (size_t)m*WROW + (size_t)ia*LF;
  unsigned* sr1 = g_scores + (size_t)m*WROW + (size_t)ib*LF;
  #pragma unroll
  for (int jj=0;jj<7;jj++){
    int j = jslot + (jj<<6);
    bool v = (jj<6) || (jslot<8);
    if (!v) continue;
    int jl0 = j - sameA;
    if (jl0>=0 && jl0<LF){
      unsigned key = 0u;
      if (j != ia){
        float wv = (a0[jj]*inv0 + 1e-6f)*rc0;
        unsigned gi = (unsigned)(m*WROW + ia*LF + jl0);
        key = __float_as_uint(__fdividef(wv, neglogu_at(gi)));
      }
      sr0[jl0] = key;
    }
    int jl1 = j - sameB;
    if (jl1>=0 && jl1<LF){
      unsigned key = 0u;
      if (j != ib){
        float wv = (a1[jj]*inv1 + 1e-6f)*rc1;
        unsigned gi = (unsigned)(m*WROW + ib*LF + jl1);
        key = __float_as_uint(__fdividef(wv, neglogu_at(gi)));
      }
      sr1[jl1] = key;
    }
  }
}

// ----------------------------------------------------------------------------
// Fused select+mask per m: 1024 threads, writes BIT-PACKED mask words.
// ----------------------------------------------------------------------------
#define SELT 1024
#define NWARP 32
#define REGION 2432   // multiple of 32; 31*2432 + 1440 = 76832

__global__ void __launch_bounds__(SELT) selmask_kernel(){
  int m = blockIdx.x, tid = threadIdx.x;
  const unsigned* row = g_scores + (size_t)m*WROW;
  unsigned* mwords = g_maskbits + (size_t)m*NWORD;
  __shared__ unsigned hist[256];
  __shared__ unsigned s_prefix;
  __shared__ int s_krem;
  __shared__ int weq[NWARP];

  unsigned prefix = 0; int krem = KSEL;
  for (int pass=0; pass<4; pass++){
    int shift = 24 - 8*pass;
    unsigned hm = pass ? (0xFFFFFFFFu << (shift+8)) : 0u;
    if (tid < 256) hist[tid] = 0;
    __syncthreads();
    for (int idx=tid; idx<WROW; idx+=SELT){
      unsigned u = row[idx];
      if ((u & hm) == prefix) atomicAdd(&hist[(u>>shift)&0xFFu], 1u);
    }
    __syncthreads();
    if (tid==0){
      int cum = 0, b = 255;
      for (; b>=0; b--){ cum += (int)hist[b]; if (cum >= krem) break; }
      int above = cum - (int)hist[b];
      s_prefix = prefix | ((unsigned)b << shift);
      s_krem = krem - above;
    }
    __syncthreads();
    prefix = s_prefix; krem = s_krem;
    __syncthreads();
  }
  const unsigned T = prefix;
  const int need = krem;

  int lane = tid & 31, w = tid >> 5;
  int lo = w*REGION, hi = min(lo + REGION, WROW);

  int ec = 0;
  for (int idx = lo + lane; idx < hi; idx += 32)
    ec += (row[idx] == T);
  #pragma unroll
  for (int o=16;o>0;o>>=1) ec += __shfl_xor_sync(0xffffffffu, ec, o);
  if (lane==0) weq[w] = ec;
  __syncthreads();
  int base = 0;
  for (int ww=0; ww<w; ww++) base += weq[ww];

  int run = base;
  for (int idx0 = lo; idx0 < hi; idx0 += 32){
    int idx = idx0 + lane;
    unsigned u = row[idx];
    bool eq = (u == T);
    unsigned bal = __ballot_sync(0xffffffffu, eq);
    int rank = run + __popc(bal & ((1u<<lane)-1u));
    bool sel = (u > T) || (eq && rank < need);
    unsigned word = __ballot_sync(0xffffffffu, sel);
    if (lane==0) mwords[idx0 >> 5] = word;
    run += __popc(bal);
  }
}

// ----------------------------------------------------------------------------
// attn kernel v5: block = (m, 8 rows), 128 threads, warp = 2 rows.
// V line loaded once serves both rows; 4 independent FMA chains.
// ----------------------------------------------------------------------------
__global__ void __launch_bounds__(128, 8) attn_kernel(){
  int blk = blockIdx.x;
  int m = blk / 49, it = blk % 49;
  int lane = threadIdx.x & 31, w = threadIdx.x >> 5;   // w in 0..3
  int i0 = it*8;
  __shared__ float l[8][Nn];

  const unsigned* mb = g_maskbits + (size_t)m*NWORD;

  #pragma unroll 1
  for (int rr=0; rr<2; rr++){
    int i = i0 + w*2 + rr;
    int same = (i >= LF) ? LF : 0;
    int base_bit = i*LF;
    int w0 = base_bit >> 5, off = base_bit & 31;
    unsigned mw[8];
    #pragma unroll
    for (int k=0;k<8;k++) mw[k] = __ldg(mb + w0 + k);  // +8 pad makes this safe

    const float* pr = g_probs + ((size_t)m*Nn + i)*Nn;
    float p[13];
    float dsum = 0.f;
    #pragma unroll
    for (int k=0;k<13;k++){
      int j = lane + 32*k;
      float v = (j < Nn) ? __ldg(pr + j) : 0.f;
      int jl = j - same;
      if (jl >= 0 && jl < LF){
        int s0 = off + 32*k - same;        // == off + jl - lane (warp-uniform)
        int wlo = s0 >> 5, sh = s0 & 31;
        unsigned f = __funnelshift_r(mw[wlo], mw[wlo+1], sh);
        if ((f >> lane) & 1u) v = 0.f;
      }
      p[k] = v;
      dsum += v;
    }
    float inv = 1.0f/warpSum(dsum);
    #pragma unroll
    for (int k=0;k<13;k++){
      int j = lane + 32*k;
      if (j < Nn) l[w*2+rr][j] = p[k]*inv;
    }
  }
  __syncwarp();

  const int r0 = w*2, r1 = r0+1;
  const float* vb = g_v + (size_t)m*Nn*HD + lane;
  const float* l0 = l[r0];
  const float* l1 = l[r1];
  float a00=0.f, a01=0.f, a10=0.f, a11=0.f;
  #pragma unroll 2
  for (int j=0; j<Nn; j+=2){
    float v0 = vb[(size_t)j*HD];
    float v1 = vb[(size_t)(j+1)*HD];
    a00 += l0[j]*v0;   a10 += l1[j]*v0;
    a01 += l0[j+1]*v1; a11 += l1[j+1]*v1;
  }
  float acc0 = a00 + a01;
  float acc1 = a10 + a11;

  int b = m >> 4, h = m & 15;
  g_o[((size_t)(b*Nn + (i0+r0)))*Cc + h*HD + lane] = acc0;
  g_o[((size_t)(b*Nn + (i0+r1)))*Cc + h*HD + lane] = acc1;
}

// ----------------------------------------------------------------------------
// Launch
// ----------------------------------------------------------------------------
extern "C" void kernel_launch(void* const* d_in, const int* in_sizes, int n_in,
                              void* d_out, int out_size){
  const float* x      = (const float*)d_in[0];
  const float* n1w    = (const float*)d_in[1];
  const float* n1b    = (const float*)d_in[2];
  const float* qkv_w  = (const float*)d_in[3];
  const float* qkv_b  = (const float*)d_in[4];
  const float* proj_w = (const float*)d_in[5];
  const float* proj_b = (const float*)d_in[6];
  const float* n2w    = (const float*)d_in[7];
  const float* n2b    = (const float*)d_in[8];
  const float* fc1_w  = (const float*)d_in[9];
  const float* fc1_b  = (const float*)d_in[10];
  const float* fc2_w  = (const float*)d_in[11];
  const float* fc2_b  = (const float*)d_in[12];
  float* out = (float*)d_out;

  float *p_h, *p_qkv, *p_o, *p_x1, *p_h2, *p_mlp;
  cudaGetSymbolAddress((void**)&p_h,   g_h);
  cudaGetSymbolAddress((void**)&p_qkv, g_qkv);
  cudaGetSymbolAddress((void**)&p_o,   g_o);
  cudaGetSymbolAddress((void**)&p_x1,  g_x1);
  cudaGetSymbolAddress((void**)&p_h2,  g_h2);
  cudaGetSymbolAddress((void**)&p_mlp, g_mlp);

  // allow >48KB dynamic smem (idempotent)
  cudaFuncSetAttribute(score_kernel,
                       cudaFuncAttributeMaxDynamicSharedMemorySize, SC_SMEM);
  cudaFuncSetAttribute(gemm_tf32,
                       cudaFuncAttributeMaxDynamicSharedMemorySize, GEMM_SMEM);

  // 1) LN1
  ln_kernel<<<ROWS, 256>>>(x, n1w, n1b, p_h);
  // 2) QKV GEMM
  gemm_tf32<<<dim3(3*Cc/128, ROWS/128), 256, GEMM_SMEM>>>(p_h, qkv_w, qkv_b, nullptr, p_qkv,
                                               ROWS, 3*Cc, Cc, 0);
  // 3) reorder to per-head Q/K/V
  reorder_qkv<<<(ROWS*3*Cc + 255)/256, 256>>>();
  // 4) QK (smem-staged, swizzled) + probs + sort keys
  score_kernel<<<Mm*49, 256, SC_SMEM>>>();
  // 5) fused top-k threshold + bit-packed mask
  selmask_kernel<<<Mm, SELT>>>();
  // 6) renormalize masked probs + AV (2 rows per warp)
  attn_kernel<<<Mm*49, 128>>>();
  // 7) proj + residual(x)
  gemm_tf32<<<dim3(Cc/128, ROWS/128), 256, GEMM_SMEM>>>(p_o, proj_w, proj_b, x, p_x1,
                                             ROWS, Cc, Cc, 0);
  // 8) LN2
  ln_kernel<<<ROWS, 256>>>(p_x1, n2w, n2b, p_h2);
  // 9) fc1 + exact gelu
  gemm_tf32<<<dim3(MLPH/128, ROWS/128), 256, GEMM_SMEM>>>(p_h2, fc1_w, fc1_b, nullptr, p_mlp,
                                               ROWS, MLPH, Cc, 1);
  // 10) fc2 + residual(x1) -> out
  gemm_tf32<<<dim3(Cc/128, ROWS/128), 256, GEMM_SMEM>>>(p_mlp, fc2_w, fc2_b, p_x1, out,
                                             ROWS, Cc, MLPH, 0);
}

// round 16
// speedup vs baseline: 1.1266x; 1.0084x over previous
#include <cuda_runtime.h>
#include <cuda_bf16.h>
#include <math.h>

// ----------------------------------------------------------------------------
// Problem constants
// ----------------------------------------------------------------------------
#define Bz   16
#define Nn   392
#define Cc   512
#define Hh   16
#define HD   32
#define Mm   (Bz*Hh)          // 256
#define LF   196              // Nn/2
#define MLPH 2048
#define ROWS (Bz*Nn)          // 6272
#define WROW (Nn*LF)          // 76832  scores per m
#define KSEL 7448             // int(0.1*195)*392
#define NWORD 2401            // WROW/32 mask words per m
#define NEGBIG (-3.4e38f)

// score kernel smem layout
#define KS_BYTES (Nn*8*16)            // 50176: K tile, float4 chunks, swizzled
#define QS_BYTES (8*32*4)             // 1024 : 8 scaled q rows
#define RED_BYTES 128                 // 4 rg x 2 wh x 4 floats
#define SC_SMEM (KS_BYTES + QS_BYTES + RED_BYTES)

// ----------------------------------------------------------------------------
// Scratch (static device globals; no allocation at runtime)
// ----------------------------------------------------------------------------
__device__ float g_h   [ROWS*Cc];
__device__ float g_qkv [ROWS*3*Cc];
__device__ float g_q   [Mm*Nn*HD];
__device__ float g_k   [Mm*Nn*HD];
__device__ float g_v   [Mm*Nn*HD];
__device__ float g_probs[(size_t)Mm*Nn*Nn];     // unmasked softmax probs
__device__ unsigned g_scores[(size_t)Mm*WROW];  // positive-float sort keys
__device__ unsigned g_maskbits[(size_t)Mm*NWORD + 8];
__device__ float g_o   [ROWS*Cc];
__device__ float g_x1  [ROWS*Cc];
__device__ float g_h2  [ROWS*Cc];
__device__ float g_mlp [ROWS*MLPH];

// ----------------------------------------------------------------------------
// Reductions
// ----------------------------------------------------------------------------
__device__ __forceinline__ float warpMax(float v){
  #pragma unroll
  for (int o=16;o>0;o>>=1) v = fmaxf(v, __shfl_xor_sync(0xffffffffu, v, o));
  return v;
}
__device__ __forceinline__ float warpSum(float v){
  #pragma unroll
  for (int o=16;o>0;o>>=1) v += __shfl_xor_sync(0xffffffffu, v, o);
  return v;
}
template<int NW>
__device__ __forceinline__ float blockSum(float v, float* sw){
  int lane = threadIdx.x & 31, w = threadIdx.x >> 5;
  v = warpSum(v);
  if (lane==0) sw[w] = v;
  __syncthreads();
  float r = 0.f;
  #pragma unroll
  for (int i=0;i<NW;i++) r += sw[i];
  __syncthreads();
  return r;
}

// ----------------------------------------------------------------------------
// JAX threefry2x32, key (0,42), partitionable 32-bit path
// ----------------------------------------------------------------------------
__device__ __forceinline__ unsigned rotl32(unsigned x, int r){ return (x<<r)|(x>>(32-r)); }
__device__ __forceinline__ unsigned threefry_bits(unsigned idx){
  const unsigned k0 = 0u, k1 = 42u;
  const unsigned k2 = k0 ^ k1 ^ 0x1BD11BDAu;
  unsigned x0 = 0u + k0;
  unsigned x1 = idx + k1;
#define TFR(r) { x0 += x1; x1 = rotl32(x1,(r)); x1 ^= x0; }
  TFR(13) TFR(15) TFR(26) TFR(6)
  x0 += k1; x1 += k2 + 1u;
  TFR(17) TFR(29) TFR(16) TFR(24)
  x0 += k2; x1 += k0 + 2u;
  TFR(13) TFR(15) TFR(26) TFR(6)
  x0 += k0; x1 += k1 + 3u;
  TFR(17) TFR(29) TFR(16) TFR(24)
  x0 += k1; x1 += k2 + 4u;
  TFR(13) TFR(15) TFR(26) TFR(6)
  x0 += k2; x1 += k0 + 5u;
#undef TFR
  return x0 ^ x1;
}
// returns -ln(u) for the gumbel draw at flat index idx  (1 MUFU log)
__device__ __forceinline__ float neglogu_at(unsigned idx){
  unsigned bits = threefry_bits(idx);
  float f = __uint_as_float((bits >> 9) | 0x3f800000u) - 1.0f;
  const float tiny = 1.17549435e-38f;
  float u = fmaxf(tiny, f + tiny);
  return -__logf(u);
}

// ----------------------------------------------------------------------------
// LayerNorm (one block per row, 256 threads, C=512)
// ----------------------------------------------------------------------------
__global__ void __launch_bounds__(256) ln_kernel(const float* __restrict__ x,
                                                 const float* __restrict__ w,
                                                 const float* __restrict__ bias,
                                                 float* __restrict__ out){
  int row = blockIdx.x, t = threadIdx.x;
  const float* xr = x + (size_t)row*Cc;
  __shared__ float sw[8];
  float a = xr[t], b = xr[t+256];
  float s = blockSum<8>(a+b, sw);
  float mu = s * (1.0f/512.0f);
  float da = a-mu, db = b-mu;
  float v = blockSum<8>(da*da + db*db, sw);
  float rstd = rsqrtf(v*(1.0f/512.0f) + 1e-5f);
  out[(size_t)row*Cc + t]     = da*rstd*w[t]     + bias[t];
  out[(size_t)row*Cc + t+256] = db*rstd*w[t+256] + bias[t+256];
}

// ----------------------------------------------------------------------------
// tf32 tensor-core GEMM, templated on BN (128 or 64): 128xBN tile, BK=16,
// 256 threads, mma.m16n8k8.tf32, cp.async 4-stage ring, one barrier per tile.
// Raw fp32 bits fed to tf32 mma. act: 0 = bias(+res), 1 = bias+gelu
// ----------------------------------------------------------------------------
__device__ __forceinline__ void cp16(float* dst, const float* src){
  unsigned d = (unsigned)__cvta_generic_to_shared(dst);
  asm volatile("cp.async.ca.shared.global [%0], [%1], 16;\n" :: "r"(d), "l"(src));
}
__device__ __forceinline__ void mma_tf32(float* c, const unsigned* a, const unsigned* b){
  asm volatile(
    "mma.sync.aligned.m16n8k8.row.col.f32.tf32.tf32.f32 "
    "{%0,%1,%2,%3},{%4,%5,%6,%7},{%8,%9},{%0,%1,%2,%3};\n"
    : "+f"(c[0]),"+f"(c[1]),"+f"(c[2]),"+f"(c[3])
    : "r"(a[0]),"r"(a[1]),"r"(a[2]),"r"(a[3]),"r"(b[0]),"r"(b[1]));
}

#define APAD 20
#define AS_STRIDE (128*APAD)                 // floats per A stage
#define GEMM_SMEM_MAX ((4*AS_STRIDE + 4*16*136)*4)   // BN=128 case: 75776 B

template<int BN>
__global__ void __launch_bounds__(256, 2) gemm_tf32(const float* __restrict__ A,
                                                 const float* __restrict__ Bw,
                                                 const float* __restrict__ bias,
                                                 const float* __restrict__ res,
                                                 float* __restrict__ C,
                                                 int M, int N, int K, int act){
  constexpr int BPAD = BN + 8;               // 136 or 72 (both stagger 8 mod 32)
  constexpr int BS_STRIDE = 16*BPAD;
  constexpr int WN = BN/32;                  // 4 or 2
  constexpr int WM = 8/WN;                   // 2 or 4
  constexpr int MT = 128/(WM*16);            // 4 or 2
  constexpr int NT = 4;                      // BN/(WN*8) = 4 for both
  constexpr int BLOADS = (16*BN/4 + 255)/256;// float4 rounds for B stage: 2 or 1

  extern __shared__ float gsm[];
  float* Asb = gsm;
  float* Bsb = gsm + 4*AS_STRIDE;
  const int tid = threadIdx.x;
  const int lane = tid & 31, wid = tid >> 5;
  const int wm = wid / WN, wn = wid % WN;
  const int bm = blockIdx.y*128, bn = blockIdx.x*BN;

  float acc[MT*NT][4];
  #pragma unroll
  for (int i=0;i<MT*NT;i++){ acc[i][0]=0.f; acc[i][1]=0.f; acc[i][2]=0.f; acc[i][3]=0.f; }

  const int nT = K >> 4;

  auto load_stage = [&](int t, int buf){
    float* As = Asb + buf*AS_STRIDE;
    float* Bs = Bsb + buf*BS_STRIDE;
    int k0 = t << 4;
    #pragma unroll
    for (int r=0;r<2;r++){        // A: 128x16 = 512 float4 = 2 rounds
      int i = tid + 256*r;
      int arow = i >> 2, ac = (i & 3) << 2;
      cp16(&As[arow*APAD + ac], A + (size_t)(bm+arow)*K + k0 + ac);
    }
    #pragma unroll
    for (int r=0;r<BLOADS;r++){   // B: 16xBN = 16*BN/4 float4
      int i = tid + 256*r;
      int brow = i / (BN/4), bc = (i % (BN/4)) << 2;
      cp16(&Bs[brow*BPAD + bc], Bw + (size_t)(k0+brow)*N + bn + bc);
    }
    asm volatile("cp.async.commit_group;\n");
  };

  // prologue: 3 stages in flight
  load_stage(0, 0);
  load_stage(1, 1);
  load_stage(2, 2);
  for (int t=0; t<nT; t++){
    if (t+2 < nT)      asm volatile("cp.async.wait_group 2;\n");
    else if (t+1 < nT) asm volatile("cp.async.wait_group 1;\n");
    else               asm volatile("cp.async.wait_group 0;\n");
    __syncthreads();   // single barrier per tile (4-stage ring makes it safe)
    const int cbuf = t & 3;
    const unsigned* as = (const unsigned*)(Asb + cbuf*AS_STRIDE);
    const unsigned* bs = (const unsigned*)(Bsb + cbuf*BS_STRIDE);
    #pragma unroll
    for (int ks=0; ks<16; ks+=8){
      unsigned a[MT][4], b[NT][2];
      #pragma unroll
      for (int mt=0;mt<MT;mt++){
        int r0 = wm*(MT*16) + mt*16 + (lane>>2);
        int cc = ks + (lane&3);
        a[mt][0] = as[r0*APAD + cc];
        a[mt][1] = as[(r0+8)*APAD + cc];
        a[mt][2] = as[r0*APAD + cc + 4];
        a[mt][3] = as[(r0+8)*APAD + cc + 4];
      }
      #pragma unroll
      for (int nt=0;nt<NT;nt++){
        int cn = wn*32 + nt*8 + (lane>>2);
        b[nt][0] = bs[(ks + (lane&3))*BPAD + cn];
        b[nt][1] = bs[(ks + 4 + (lane&3))*BPAD + cn];
      }
      #pragma unroll
      for (int mt=0;mt<MT;mt++)
        #pragma unroll
        for (int nt=0;nt<NT;nt++)
          mma_tf32(acc[mt*NT+nt], a[mt], b[nt]);
    }
    if (t+3 < nT) load_stage(t+3, (t+3) & 3);
  }

  #pragma unroll
  for (int mt=0;mt<MT;mt++){
    #pragma unroll
    for (int nt=0;nt<NT;nt++){
      float* c = acc[mt*NT+nt];
      int gm = bm + wm*(MT*16) + mt*16 + (lane>>2);
      int gn = bn + wn*32 + nt*8 + ((lane&3)<<1);
      float b0 = bias[gn], b1 = bias[gn+1];
      #pragma unroll
      for (int hrow=0; hrow<2; hrow++){
        int gr = gm + hrow*8;
        float v0 = c[hrow*2+0] + b0;
        float v1 = c[hrow*2+1] + b1;
        if (act==1){
          v0 = 0.5f*v0*(1.0f + erff(v0*0.70710678118654752440f));
          v1 = 0.5f*v1*(1.0f + erff(v1*0.70710678118654752440f));
        }
        if (res){
          v0 += res[(size_t)gr*N + gn];
          v1 += res[(size_t)gr*N + gn+1];
        }
        C[(size_t)gr*N + gn]   = v0;
        C[(size_t)gr*N + gn+1] = v1;
      }
    }
  }
}

// ----------------------------------------------------------------------------
// QKV reorder: [row=b*392+i][3*512] -> Q/K/V [m=b*16+h][i][d]
// ----------------------------------------------------------------------------
__global__ void reorder_qkv(){
  int idx = blockIdx.x*blockDim.x + threadIdx.x;
  if (idx >= ROWS*3*Cc) return;
  int r = idx / (3*Cc), c = idx % (3*Cc);
  int which = c >> 9;
  int cc = c & 511;
  int h = cc >> 5, d = cc & 31;
  int b = r / Nn, i = r % Nn;
  float v = g_qkv[idx];
  size_t dst = ((size_t)((b*Hh+h)*Nn + i))*HD + d;
  if (which==0) g_q[dst]=v; else if (which==1) g_k[dst]=v; else g_v[dst]=v;
}

// ----------------------------------------------------------------------------
// score kernel v4 (measured 311us): block = (m, 8 query rows), 256 threads.
// ----------------------------------------------------------------------------
__global__ void __launch_bounds__(256) score_kernel(){
  extern __shared__ char sraw[];
  float4* ks  = (float4*)sraw;
  float*  qs  = (float*)(sraw + KS_BYTES);
  float*  red = (float*)(sraw + KS_BYTES + QS_BYTES);   // [4 rg][2 wh][4]

  int blk = blockIdx.x;
  int m = blk / 49, it = blk % 49;
  int i0 = it*8;
  int tid = threadIdx.x, lane = tid & 31;

  {
    int i = tid >> 5, d = tid & 31;
    qs[i*32 + d] = g_q[((size_t)m*Nn + i0 + i)*HD + d] * 0.17677669529663687f;
  }
  const float4* kg = (const float4*)(g_k + (size_t)m*Nn*HD);
  #pragma unroll 1
  for (int c = tid; c < Nn*8; c += 256){
    int j = c >> 3, ch = c & 7;
    ks[(j<<3) | (ch ^ (j & 7))] = kg[c];
  }
  __syncthreads();

  const int rg = tid >> 6;
  const int jslot = tid & 63;
  const int wh = (tid >> 5) & 1;
  const int sw = jslot & 7;
  const int r0 = rg*2, r1 = r0+1;

  float a0[7], a1[7];
  #pragma unroll
  for (int jj=0;jj<7;jj++){ a0[jj]=0.f; a1[jj]=0.f; }

  #pragma unroll
  for (int t=0;t<8;t++){
    float4 qa = *(const float4*)&qs[r0*32 + t*4];
    float4 qb = *(const float4*)&qs[r1*32 + t*4];
    #pragma unroll
    for (int jj=0;jj<7;jj++){
      int j = jslot + (jj<<6);
      int jbase = (jj<6 || jslot<8) ? j : jslot;
      float4 kv = ks[(jbase<<3) | (t ^ sw)];
      a0[jj] += kv.x*qa.x + kv.y*qa.y + kv.z*qa.z + kv.w*qa.w;
      a1[jj] += kv.x*qb.x + kv.y*qb.y + kv.z*qb.z + kv.w*qb.w;
    }
  }

  const int ia = i0 + r0, ib = i0 + r1;
  const int sameA = (ia>=LF)?LF:0, sameB = (ib>=LF)?LF:0;

  float lm0=NEGBIG, lm1=NEGBIG, cm0=NEGBIG, cm1=NEGBIG;
  #pragma unroll
  for (int jj=0;jj<7;jj++){
    int j = jslot + (jj<<6);
    bool v = (jj<6) || (jslot<8);
    if (v){
      lm0 = fmaxf(lm0, a0[jj]);
      lm1 = fmaxf(lm1, a1[jj]);
      bool crA = sameA ? (j<LF) : (j>=LF);
      bool crB = sameB ? (j<LF) : (j>=LF);
      if (crA) cm0 = fmaxf(cm0, a0[jj]);
      if (crB) cm1 = fmaxf(cm1, a1[jj]);
    }
  }
  lm0=warpMax(lm0); lm1=warpMax(lm1); cm0=warpMax(cm0); cm1=warpMax(cm1);
  if (lane==0){
    float* rr = red + (rg*2+wh)*4;
    rr[0]=lm0; rr[1]=lm1; rr[2]=cm0; rr[3]=cm1;
  }
  __syncthreads();
  const float* rA = red + (rg*2+0)*4;
  const float* rB = red + (rg*2+1)*4;
  float mx0 = fmaxf(rA[0], rB[0]);
  float mx1 = fmaxf(rA[1], rB[1]);
  float cx0 = fmaxf(rA[2], rB[2]);
  float cx1 = fmaxf(rA[3], rB[3]);

  float s0=0.f, s1=0.f;
  #pragma unroll
  for (int jj=0;jj<7;jj++){
    bool v = (jj<6) || (jslot<8);
    float e0 = v ? __expf(a0[jj]-mx0) : 0.f;
    float e1 = v ? __expf(a1[jj]-mx1) : 0.f;
    a0[jj]=e0; a1[jj]=e1;
    s0+=e0; s1+=e1;
  }
  s0=warpSum(s0); s1=warpSum(s1);
  __syncthreads();
  if (lane==0){ float* rr = red + (rg*2+wh)*4; rr[0]=s0; rr[1]=s1; }
  __syncthreads();
  float inv0 = 1.0f/(rA[0]+rB[0]);
  float inv1 = 1.0f/(rA[1]+rB[1]);
  float aq0 = __expf(cx0-mx0)*inv0 + 1e-6f;
  float aq1 = __expf(cx1-mx1)*inv1 + 1e-6f;

  float* pr0 = g_probs + ((size_t)m*Nn + ia)*Nn;
  float* pr1 = g_probs + ((size_t)m*Nn + ib)*Nn;
  #pragma unroll
  for (int jj=0;jj<7;jj++){
    int j = jslot + (jj<<6);
    bool v = (jj<6) || (jslot<8);
    if (v){ pr0[j] = a0[jj]*inv0; pr1[j] = a1[jj]*inv1; }
  }

  float ss0=0.f, ss1=0.f;
  #pragma unroll
  for (int jj=0;jj<7;jj++){
    int j = jslot + (jj<<6);
    bool v = (jj<6) || (jslot<8);
    if (v){
      int jl0 = j - sameA;
      if (jl0>=0 && jl0<LF && j!=ia) ss0 += a0[jj]*inv0 + 1e-6f;
      int jl1 = j - sameB;
      if (jl1>=0 && jl1<LF && j!=ib) ss1 += a1[jj]*inv1 + 1e-6f;
    }
  }
  ss0=warpSum(ss0); ss1=warpSum(ss1);
  __syncthreads();
  if (lane==0){ float* rr = red + (rg*2+wh)*4; rr[2]=ss0; rr[3]=ss1; }
  __syncthreads();
  float rc0 = aq0 / (rA[2]+rB[2]);
  float rc1 = aq1 / (rA[3]+rB[3]);

  unsigned* sr0 = g_scores + (size_t)m*WROW + (size_t)ia*LF;
  unsigned* sr1 = g_scores + (size_t)m*WROW + (size_t)ib*LF;
  #pragma unroll
  for (int jj=0;jj<7;jj++){
    int j = jslot + (jj<<6);
    bool v = (jj<6) || (jslot<8);
    if (!v) continue;
    int jl0 = j - sameA;
    if (jl0>=0 && jl0<LF){
      unsigned key = 0u;
      if (j != ia){
        float wv = (a0[jj]*inv0 + 1e-6f)*rc0;
        unsigned gi = (unsigned)(m*WROW + ia*LF + jl0);
        key = __float_as_uint(__fdividef(wv, neglogu_at(gi)));
      }
      sr0[jl0] = key;
    }
    int jl1 = j - sameB;
    if (jl1>=0 && jl1<LF){
      unsigned key = 0u;
      if (j != ib){
        float wv = (a1[jj]*inv1 + 1e-6f)*rc1;
        unsigned gi = (unsigned)(m*WROW + ib*LF + jl1);
        key = __float_as_uint(__fdividef(wv, neglogu_at(gi)));
      }
      sr1[jl1] = key;
    }
  }
}

// ----------------------------------------------------------------------------
// Fused select+mask per m: 1024 threads, writes BIT-PACKED mask words.
// ----------------------------------------------------------------------------
#define SELT 1024
#define NWARP 32
#define REGION 2432   // multiple of 32; 31*2432 + 1440 = 76832

__global__ void __launch_bounds__(SELT) selmask_kernel(){
  int m = blockIdx.x, tid = threadIdx.x;
  const unsigned* row = g_scores + (size_t)m*WROW;
  unsigned* mwords = g_maskbits + (size_t)m*NWORD;
  __shared__ unsigned hist[256];
  __shared__ unsigned s_prefix;
  __shared__ int s_krem;
  __shared__ int weq[NWARP];

  unsigned prefix = 0; int krem = KSEL;
  for (int pass=0; pass<4; pass++){
    int shift = 24 - 8*pass;
    unsigned hm = pass ? (0xFFFFFFFFu << (shift+8)) : 0u;
    if (tid < 256) hist[tid] = 0;
    __syncthreads();
    for (int idx=tid; idx<WROW; idx+=SELT){
      unsigned u = row[idx];
      if ((u & hm) == prefix) atomicAdd(&hist[(u>>shift)&0xFFu], 1u);
    }
    __syncthreads();
    if (tid==0){
      int cum = 0, b = 255;
      for (; b>=0; b--){ cum += (int)hist[b]; if (cum >= krem) break; }
      int above = cum - (int)hist[b];
      s_prefix = prefix | ((unsigned)b << shift);
      s_krem = krem - above;
    }
    __syncthreads();
    prefix = s_prefix; krem = s_krem;
    __syncthreads();
  }
  const unsigned T = prefix;
  const int need = krem;

  int lane = tid & 31, w = tid >> 5;
  int lo = w*REGION, hi = min(lo + REGION, WROW);

  int ec = 0;
  for (int idx = lo + lane; idx < hi; idx += 32)
    ec += (row[idx] == T);
  #pragma unroll
  for (int o=16;o>0;o>>=1) ec += __shfl_xor_sync(0xffffffffu, ec, o);
  if (lane==0) weq[w] = ec;
  __syncthreads();
  int base = 0;
  for (int ww=0; ww<w; ww++) base += weq[ww];

  int run = base;
  for (int idx0 = lo; idx0 < hi; idx0 += 32){
    int idx = idx0 + lane;
    unsigned u = row[idx];
    bool eq = (u == T);
    unsigned bal = __ballot_sync(0xffffffffu, eq);
    int rank = run + __popc(bal & ((1u<<lane)-1u));
    bool sel = (u > T) || (eq && rank < need);
    unsigned word = __ballot_sync(0xffffffffu, sel);
    if (lane==0) mwords[idx0 >> 5] = word;
    run += __popc(bal);
  }
}

// ----------------------------------------------------------------------------
// attn kernel v5: block = (m, 8 rows), 128 threads, warp = 2 rows.
// ----------------------------------------------------------------------------
__global__ void __launch_bounds__(128, 8) attn_kernel(){
  int blk = blockIdx.x;
  int m = blk / 49, it = blk % 49;
  int lane = threadIdx.x & 31, w = threadIdx.x >> 5;   // w in 0..3
  int i0 = it*8;
  __shared__ float l[8][Nn];

  const unsigned* mb = g_maskbits + (size_t)m*NWORD;

  #pragma unroll 1
  for (int rr=0; rr<2; rr++){
    int i = i0 + w*2 + rr;
    int same = (i >= LF) ? LF : 0;
    int base_bit = i*LF;
    int w0 = base_bit >> 5, off = base_bit & 31;
    unsigned mw[8];
    #pragma unroll
    for (int k=0;k<8;k++) mw[k] = __ldg(mb + w0 + k);  // +8 pad makes this safe

    const float* pr = g_probs + ((size_t)m*Nn + i)*Nn;
    float p[13];
    float dsum = 0.f;
    #pragma unroll
    for (int k=0;k<13;k++){
      int j = lane + 32*k;
      float v = (j < Nn) ? __ldg(pr + j) : 0.f;
      int jl = j - same;
      if (jl >= 0 && jl < LF){
        int s0 = off + 32*k - same;
        int wlo = s0 >> 5, sh = s0 & 31;
        unsigned f = __funnelshift_r(mw[wlo], mw[wlo+1], sh);
        if ((f >> lane) & 1u) v = 0.f;
      }
      p[k] = v;
      dsum += v;
    }
    float inv = 1.0f/warpSum(dsum);
    #pragma unroll
    for (int k=0;k<13;k++){
      int j = lane + 32*k;
      if (j < Nn) l[w*2+rr][j] = p[k]*inv;
    }
  }
  __syncwarp();

  const int r0 = w*2, r1 = r0+1;
  const float* vb = g_v + (size_t)m*Nn*HD + lane;
  const float* l0 = l[r0];
  const float* l1 = l[r1];
  float a00=0.f, a01=0.f, a10=0.f, a11=0.f;
  #pragma unroll 2
  for (int j=0; j<Nn; j+=2){
    float v0 = vb[(size_t)j*HD];
    float v1 = vb[(size_t)(j+1)*HD];
    a00 += l0[j]*v0;   a10 += l1[j]*v0;
    a01 += l0[j+1]*v1; a11 += l1[j+1]*v1;
  }
  float acc0 = a00 + a01;
  float acc1 = a10 + a11;

  int b = m >> 4, h = m & 15;
  g_o[((size_t)(b*Nn + (i0+r0)))*Cc + h*HD + lane] = acc0;
  g_o[((size_t)(b*Nn + (i0+r1)))*Cc + h*HD + lane] = acc1;
}

// ----------------------------------------------------------------------------
// Launch
// ----------------------------------------------------------------------------
extern "C" void kernel_launch(void* const* d_in, const int* in_sizes, int n_in,
                              void* d_out, int out_size){
  const float* x      = (const float*)d_in[0];
  const float* n1w    = (const float*)d_in[1];
  const float* n1b    = (const float*)d_in[2];
  const float* qkv_w  = (const float*)d_in[3];
  const float* qkv_b  = (const float*)d_in[4];
  const float* proj_w = (const float*)d_in[5];
  const float* proj_b = (const float*)d_in[6];
  const float* n2w    = (const float*)d_in[7];
  const float* n2b    = (const float*)d_in[8];
  const float* fc1_w  = (const float*)d_in[9];
  const float* fc1_b  = (const float*)d_in[10];
  const float* fc2_w  = (const float*)d_in[11];
  const float* fc2_b  = (const float*)d_in[12];
  float* out = (float*)d_out;

  float *p_h, *p_qkv, *p_o, *p_x1, *p_h2, *p_mlp;
  cudaGetSymbolAddress((void**)&p_h,   g_h);
  cudaGetSymbolAddress((void**)&p_qkv, g_qkv);
  cudaGetSymbolAddress((void**)&p_o,   g_o);
  cudaGetSymbolAddress((void**)&p_x1,  g_x1);
  cudaGetSymbolAddress((void**)&p_h2,  g_h2);
  cudaGetSymbolAddress((void**)&p_mlp, g_mlp);

  // allow >48KB dynamic smem (idempotent)
  cudaFuncSetAttribute(score_kernel,
                       cudaFuncAttributeMaxDynamicSharedMemorySize, SC_SMEM);
  cudaFuncSetAttribute(gemm_tf32<128>,
                       cudaFuncAttributeMaxDynamicSharedMemorySize, GEMM_SMEM_MAX);
  cudaFuncSetAttribute(gemm_tf32<64>,
                       cudaFuncAttributeMaxDynamicSharedMemorySize, GEMM_SMEM_MAX);

  const int smem128 = (4*AS_STRIDE + 4*16*136)*4;
  const int smem64  = (4*AS_STRIDE + 4*16*72)*4;

  // 1) LN1
  ln_kernel<<<ROWS, 256>>>(x, n1w, n1b, p_h);
  // 2) QKV GEMM (wide: BN=128)
  gemm_tf32<128><<<dim3(3*Cc/128, ROWS/128), 256, smem128>>>(p_h, qkv_w, qkv_b, nullptr, p_qkv,
                                               ROWS, 3*Cc, Cc, 0);
  // 3) reorder to per-head Q/K/V
  reorder_qkv<<<(ROWS*3*Cc + 255)/256, 256>>>();
  // 4) QK (smem-staged, swizzled) + probs + sort keys
  score_kernel<<<Mm*49, 256, SC_SMEM>>>();
  // 5) fused top-k threshold + bit-packed mask
  selmask_kernel<<<Mm, SELT>>>();
  // 6) renormalize masked probs + AV (2 rows per warp)
  attn_kernel<<<Mm*49, 128>>>();
  // 7) proj + residual(x)  (narrow: BN=64 -> 392 blocks, fills the chip)
  gemm_tf32<64><<<dim3(Cc/64, ROWS/128), 256, smem64>>>(p_o, proj_w, proj_b, x, p_x1,
                                             ROWS, Cc, Cc, 0);
  // 8) LN2
  ln_kernel<<<ROWS, 256>>>(p_x1, n2w, n2b, p_h2);
  // 9) fc1 + exact gelu (BN=128)
  gemm_tf32<128><<<dim3(MLPH/128, ROWS/128), 256, smem128>>>(p_h2, fc1_w, fc1_b, nullptr, p_mlp,
                                               ROWS, MLPH, Cc, 1);
  // 10) fc2 + residual(x1) -> out  (BN=64)
  gemm_tf32<64><<<dim3(Cc/64, ROWS/128), 256, smem64>>>(p_mlp, fc2_w, fc2_b, p_x1, out,
                                             ROWS, Cc, MLPH, 0);
}

// round 17
// speedup vs baseline: 1.1323x; 1.0051x over previous
#include <cuda_runtime.h>
#include <cuda_bf16.h>
#include <cuda_fp16.h>
#include <math.h>

// ----------------------------------------------------------------------------
// Problem constants
// ----------------------------------------------------------------------------
#define Bz   16
#define Nn   392
#define Cc   512
#define Hh   16
#define HD   32
#define Mm   (Bz*Hh)          // 256
#define LF   196              // Nn/2
#define MLPH 2048
#define ROWS (Bz*Nn)          // 6272
#define WROW (Nn*LF)          // 76832  scores per m
#define KSEL 7448             // int(0.1*195)*392
#define NWORD 2401            // WROW/32 mask words per m
#define NEGBIG (-3.4e38f)

// score kernel smem layout
#define KS_BYTES (Nn*8*16)            // 50176: K tile, float4 chunks, swizzled
#define QS_BYTES (8*32*4)             // 1024 : 8 scaled q rows
#define RED_BYTES 128                 // 4 rg x 2 wh x 4 floats
#define SC_SMEM (KS_BYTES + QS_BYTES + RED_BYTES)

// ----------------------------------------------------------------------------
// Scratch (static device globals; no allocation at runtime)
// ----------------------------------------------------------------------------
__device__ float g_h   [ROWS*Cc];
__device__ float g_qkv [ROWS*3*Cc];
__device__ float g_q   [Mm*Nn*HD];
__device__ float g_k   [Mm*Nn*HD];
__device__ float g_v   [Mm*Nn*HD];
__device__ __half g_probs[(size_t)Mm*Nn*Nn];    // unmasked softmax probs (fp16)
__device__ unsigned g_scores[(size_t)Mm*WROW];  // positive-float sort keys
__device__ unsigned g_maskbits[(size_t)Mm*NWORD + 8];
__device__ float g_o   [ROWS*Cc];
__device__ float g_x1  [ROWS*Cc];
__device__ float g_h2  [ROWS*Cc];
__device__ float g_mlp [ROWS*MLPH];

// ----------------------------------------------------------------------------
// Reductions
// ----------------------------------------------------------------------------
__device__ __forceinline__ float warpMax(float v){
  #pragma unroll
  for (int o=16;o>0;o>>=1) v = fmaxf(v, __shfl_xor_sync(0xffffffffu, v, o));
  return v;
}
__device__ __forceinline__ float warpSum(float v){
  #pragma unroll
  for (int o=16;o>0;o>>=1) v += __shfl_xor_sync(0xffffffffu, v, o);
  return v;
}
template<int NW>
__device__ __forceinline__ float blockSum(float v, float* sw){
  int lane = threadIdx.x & 31, w = threadIdx.x >> 5;
  v = warpSum(v);
  if (lane==0) sw[w] = v;
  __syncthreads();
  float r = 0.f;
  #pragma unroll
  for (int i=0;i<NW;i++) r += sw[i];
  __syncthreads();
  return r;
}

// ----------------------------------------------------------------------------
// JAX threefry2x32, key (0,42), partitionable 32-bit path
// ----------------------------------------------------------------------------
__device__ __forceinline__ unsigned rotl32(unsigned x, int r){ return (x<<r)|(x>>(32-r)); }
__device__ __forceinline__ unsigned threefry_bits(unsigned idx){
  const unsigned k0 = 0u, k1 = 42u;
  const unsigned k2 = k0 ^ k1 ^ 0x1BD11BDAu;
  unsigned x0 = 0u + k0;
  unsigned x1 = idx + k1;
#define TFR(r) { x0 += x1; x1 = rotl32(x1,(r)); x1 ^= x0; }
  TFR(13) TFR(15) TFR(26) TFR(6)
  x0 += k1; x1 += k2 + 1u;
  TFR(17) TFR(29) TFR(16) TFR(24)
  x0 += k2; x1 += k0 + 2u;
  TFR(13) TFR(15) TFR(26) TFR(6)
  x0 += k0; x1 += k1 + 3u;
  TFR(17) TFR(29) TFR(16) TFR(24)
  x0 += k1; x1 += k2 + 4u;
  TFR(13) TFR(15) TFR(26) TFR(6)
  x0 += k2; x1 += k0 + 5u;
#undef TFR
  return x0 ^ x1;
}
// returns -ln(u) for the gumbel draw at flat index idx  (1 MUFU log)
__device__ __forceinline__ float neglogu_at(unsigned idx){
  unsigned bits = threefry_bits(idx);
  float f = __uint_as_float((bits >> 9) | 0x3f800000u) - 1.0f;
  const float tiny = 1.17549435e-38f;
  float u = fmaxf(tiny, f + tiny);
  return -__logf(u);
}

// ----------------------------------------------------------------------------
// LayerNorm (one block per row, 256 threads, C=512)
// ----------------------------------------------------------------------------
__global__ void __launch_bounds__(256) ln_kernel(const float* __restrict__ x,
                                                 const float* __restrict__ w,
                                                 const float* __restrict__ bias,
                                                 float* __restrict__ out){
  int row = blockIdx.x, t = threadIdx.x;
  const float* xr = x + (size_t)row*Cc;
  __shared__ float sw[8];
  float a = xr[t], b = xr[t+256];
  float s = blockSum<8>(a+b, sw);
  float mu = s * (1.0f/512.0f);
  float da = a-mu, db = b-mu;
  float v = blockSum<8>(da*da + db*db, sw);
  float rstd = rsqrtf(v*(1.0f/512.0f) + 1e-5f);
  out[(size_t)row*Cc + t]     = da*rstd*w[t]     + bias[t];
  out[(size_t)row*Cc + t+256] = db*rstd*w[t+256] + bias[t+256];
}

// ----------------------------------------------------------------------------
// tf32 tensor-core GEMM, templated on BN (128/64) and ACT:
//   ACT 0 = bias(+res), 1 = bias+gelu, 2 = bias + QKV scatter (qkv only)
// 128xBN tile, BK=16, 256 threads, mma.m16n8k8.tf32, cp.async 4-stage ring,
// one barrier per tile. Raw fp32 bits fed to tf32 mma.
// ----------------------------------------------------------------------------
__device__ __forceinline__ void cp16(float* dst, const float* src){
  unsigned d = (unsigned)__cvta_generic_to_shared(dst);
  asm volatile("cp.async.ca.shared.global [%0], [%1], 16;\n" :: "r"(d), "l"(src));
}
__device__ __forceinline__ void mma_tf32(float* c, const unsigned* a, const unsigned* b){
  asm volatile(
    "mma.sync.aligned.m16n8k8.row.col.f32.tf32.tf32.f32 "
    "{%0,%1,%2,%3},{%4,%5,%6,%7},{%8,%9},{%0,%1,%2,%3};\n"
    : "+f"(c[0]),"+f"(c[1]),"+f"(c[2]),"+f"(c[3])
    : "r"(a[0]),"r"(a[1]),"r"(a[2]),"r"(a[3]),"r"(b[0]),"r"(b[1]));
}

#define APAD 20
#define AS_STRIDE (128*APAD)                 // floats per A stage
#define GEMM_SMEM_MAX ((4*AS_STRIDE + 4*16*136)*4)   // BN=128 case: 75776 B

template<int BN, int ACT>
__global__ void __launch_bounds__(256, 2) gemm_tf32(const float* __restrict__ A,
                                                 const float* __restrict__ Bw,
                                                 const float* __restrict__ bias,
                                                 const float* __restrict__ res,
                                                 float* __restrict__ C,
                                                 int M, int N, int K){
  constexpr int BPAD = BN + 8;               // 136 or 72 (both stagger 8 mod 32)
  constexpr int BS_STRIDE = 16*BPAD;
  constexpr int WN = BN/32;                  // 4 or 2
  constexpr int WM = 8/WN;                   // 2 or 4
  constexpr int MT = 128/(WM*16);            // 4 or 2
  constexpr int NT = 4;
  constexpr int BLOADS = (16*BN/4 + 255)/256;

  extern __shared__ float gsm[];
  float* Asb = gsm;
  float* Bsb = gsm + 4*AS_STRIDE;
  const int tid = threadIdx.x;
  const int lane = tid & 31, wid = tid >> 5;
  const int wm = wid / WN, wn = wid % WN;
  const int bm = blockIdx.y*128, bn = blockIdx.x*BN;

  float acc[MT*NT][4];
  #pragma unroll
  for (int i=0;i<MT*NT;i++){ acc[i][0]=0.f; acc[i][1]=0.f; acc[i][2]=0.f; acc[i][3]=0.f; }

  const int nT = K >> 4;

  auto load_stage = [&](int t, int buf){
    float* As = Asb + buf*AS_STRIDE;
    float* Bs = Bsb + buf*BS_STRIDE;
    int k0 = t << 4;
    #pragma unroll
    for (int r=0;r<2;r++){
      int i = tid + 256*r;
      int arow = i >> 2, ac = (i & 3) << 2;
      cp16(&As[arow*APAD + ac], A + (size_t)(bm+arow)*K + k0 + ac);
    }
    #pragma unroll
    for (int r=0;r<BLOADS;r++){
      int i = tid + 256*r;
      int brow = i / (BN/4), bc = (i % (BN/4)) << 2;
      cp16(&Bs[brow*BPAD + bc], Bw + (size_t)(k0+brow)*N + bn + bc);
    }
    asm volatile("cp.async.commit_group;\n");
  };

  load_stage(0, 0);
  load_stage(1, 1);
  load_stage(2, 2);
  for (int t=0; t<nT; t++){
    if (t+2 < nT)      asm volatile("cp.async.wait_group 2;\n");
    else if (t+1 < nT) asm volatile("cp.async.wait_group 1;\n");
    else               asm volatile("cp.async.wait_group 0;\n");
    __syncthreads();
    const int cbuf = t & 3;
    const unsigned* as = (const unsigned*)(Asb + cbuf*AS_STRIDE);
    const unsigned* bs = (const unsigned*)(Bsb + cbuf*BS_STRIDE);
    #pragma unroll
    for (int ks=0; ks<16; ks+=8){
      unsigned a[MT][4], b[NT][2];
      #pragma unroll
      for (int mt=0;mt<MT;mt++){
        int r0 = wm*(MT*16) + mt*16 + (lane>>2);
        int cc = ks + (lane&3);
        a[mt][0] = as[r0*APAD + cc];
        a[mt][1] = as[(r0+8)*APAD + cc];
        a[mt][2] = as[r0*APAD + cc + 4];
        a[mt][3] = as[(r0+8)*APAD + cc + 4];
      }
      #pragma unroll
      for (int nt=0;nt<NT;nt++){
        int cn = wn*32 + nt*8 + (lane>>2);
        b[nt][0] = bs[(ks + (lane&3))*BPAD + cn];
        b[nt][1] = bs[(ks + 4 + (lane&3))*BPAD + cn];
      }
      #pragma unroll
      for (int mt=0;mt<MT;mt++)
        #pragma unroll
        for (int nt=0;nt<NT;nt++)
          mma_tf32(acc[mt*NT+nt], a[mt], b[nt]);
    }
    if (t+3 < nT) load_stage(t+3, (t+3) & 3);
  }

  #pragma unroll
  for (int mt=0;mt<MT;mt++){
    #pragma unroll
    for (int nt=0;nt<NT;nt++){
      float* c = acc[mt*NT+nt];
      int gm = bm + wm*(MT*16) + mt*16 + (lane>>2);
      int gn = bn + wn*32 + nt*8 + ((lane&3)<<1);
      float b0 = bias[gn], b1 = bias[gn+1];
      #pragma unroll
      for (int hrow=0; hrow<2; hrow++){
        int gr = gm + hrow*8;
        float v0 = c[hrow*2+0] + b0;
        float v1 = c[hrow*2+1] + b1;
        if (ACT==1){
          v0 = 0.5f*v0*(1.0f + erff(v0*0.70710678118654752440f));
          v1 = 0.5f*v1*(1.0f + erff(v1*0.70710678118654752440f));
        }
        if (ACT==2){
          // qkv scatter: gr = b*392+i, gn in [0,1536)
          int bb = gr / Nn, ii = gr - bb*Nn;
          int which = gn >> 9;
          int cc = gn & 511;
          int h = cc >> 5, d = cc & 31;      // gn even -> d<=30, d+1 same head
          float* dst = (which==0) ? g_q : (which==1) ? g_k : g_v;
          size_t off = ((size_t)((bb*Hh + h)*Nn + ii))*HD + d;
          dst[off]   = v0;
          dst[off+1] = v1;
        } else {
          if (res){
            v0 += res[(size_t)gr*N + gn];
            v1 += res[(size_t)gr*N + gn+1];
          }
          C[(size_t)gr*N + gn]   = v0;
          C[(size_t)gr*N + gn+1] = v1;
        }
      }
    }
  }
}

// ----------------------------------------------------------------------------
// score kernel v4: block = (m, 8 query rows), 256 threads. fp16 probs out.
// ----------------------------------------------------------------------------
__global__ void __launch_bounds__(256) score_kernel(){
  extern __shared__ char sraw[];
  float4* ks  = (float4*)sraw;
  float*  qs  = (float*)(sraw + KS_BYTES);
  float*  red = (float*)(sraw + KS_BYTES + QS_BYTES);   // [4 rg][2 wh][4]

  int blk = blockIdx.x;
  int m = blk / 49, it = blk % 49;
  int i0 = it*8;
  int tid = threadIdx.x, lane = tid & 31;

  {
    int i = tid >> 5, d = tid & 31;
    qs[i*32 + d] = g_q[((size_t)m*Nn + i0 + i)*HD + d] * 0.17677669529663687f;
  }
  const float4* kg = (const float4*)(g_k + (size_t)m*Nn*HD);
  #pragma unroll 1
  for (int c = tid; c < Nn*8; c += 256){
    int j = c >> 3, ch = c & 7;
    ks[(j<<3) | (ch ^ (j & 7))] = kg[c];
  }
  __syncthreads();

  const int rg = tid >> 6;
  const int jslot = tid & 63;
  const int wh = (tid >> 5) & 1;
  const int sw = jslot & 7;
  const int r0 = rg*2, r1 = r0+1;

  float a0[7], a1[7];
  #pragma unroll
  for (int jj=0;jj<7;jj++){ a0[jj]=0.f; a1[jj]=0.f; }

  #pragma unroll
  for (int t=0;t<8;t++){
    float4 qa = *(const float4*)&qs[r0*32 + t*4];
    float4 qb = *(const float4*)&qs[r1*32 + t*4];
    #pragma unroll
    for (int jj=0;jj<7;jj++){
      int j = jslot + (jj<<6);
      int jbase = (jj<6 || jslot<8) ? j : jslot;
      float4 kv = ks[(jbase<<3) | (t ^ sw)];
      a0[jj] += kv.x*qa.x + kv.y*qa.y + kv.z*qa.z + kv.w*qa.w;
      a1[jj] += kv.x*qb.x + kv.y*qb.y + kv.z*qb.z + kv.w*qb.w;
    }
  }

  const int ia = i0 + r0, ib = i0 + r1;
  const int sameA = (ia>=LF)?LF:0, sameB = (ib>=LF)?LF:0;

  float lm0=NEGBIG, lm1=NEGBIG, cm0=NEGBIG, cm1=NEGBIG;
  #pragma unroll
  for (int jj=0;jj<7;jj++){
    int j = jslot + (jj<<6);
    bool v = (jj<6) || (jslot<8);
    if (v){
      lm0 = fmaxf(lm0, a0[jj]);
      lm1 = fmaxf(lm1, a1[jj]);
      bool crA = sameA ? (j<LF) : (j>=LF);
      bool crB = sameB ? (j<LF) : (j>=LF);
      if (crA) cm0 = fmaxf(cm0, a0[jj]);
      if (crB) cm1 = fmaxf(cm1, a1[jj]);
    }
  }
  lm0=warpMax(lm0); lm1=warpMax(lm1); cm0=warpMax(cm0); cm1=warpMax(cm1);
  if (lane==0){
    float* rr = red + (rg*2+wh)*4;
    rr[0]=lm0; rr[1]=lm1; rr[2]=cm0; rr[3]=cm1;
  }
  __syncthreads();
  const float* rA = red + (rg*2+0)*4;
  const float* rB = red + (rg*2+1)*4;
  float mx0 = fmaxf(rA[0], rB[0]);
  float mx1 = fmaxf(rA[1], rB[1]);
  float cx0 = fmaxf(rA[2], rB[2]);
  float cx1 = fmaxf(rA[3], rB[3]);

  float s0=0.f, s1=0.f;
  #pragma unroll
  for (int jj=0;jj<7;jj++){
    bool v = (jj<6) || (jslot<8);
    float e0 = v ? __expf(a0[jj]-mx0) : 0.f;
    float e1 = v ? __expf(a1[jj]-mx1) : 0.f;
    a0[jj]=e0; a1[jj]=e1;
    s0+=e0; s1+=e1;
  }
  s0=warpSum(s0); s1=warpSum(s1);
  __syncthreads();
  if (lane==0){ float* rr = red + (rg*2+wh)*4; rr[0]=s0; rr[1]=s1; }
  __syncthreads();
  float inv0 = 1.0f/(rA[0]+rB[0]);
  float inv1 = 1.0f/(rA[1]+rB[1]);
  float aq0 = __expf(cx0-mx0)*inv0 + 1e-6f;
  float aq1 = __expf(cx1-mx1)*inv1 + 1e-6f;

  __half* pr0 = g_probs + ((size_t)m*Nn + ia)*Nn;
  __half* pr1 = g_probs + ((size_t)m*Nn + ib)*Nn;
  #pragma unroll
  for (int jj=0;jj<7;jj++){
    int j = jslot + (jj<<6);
    bool v = (jj<6) || (jslot<8);
    if (v){
      pr0[j] = __float2half_rn(a0[jj]*inv0);
      pr1[j] = __float2half_rn(a1[jj]*inv1);
    }
  }

  float ss0=0.f, ss1=0.f;
  #pragma unroll
  for (int jj=0;jj<7;jj++){
    int j = jslot + (jj<<6);
    bool v = (jj<6) || (jslot<8);
    if (v){
      int jl0 = j - sameA;
      if (jl0>=0 && jl0<LF && j!=ia) ss0 += a0[jj]*inv0 + 1e-6f;
      int jl1 = j - sameB;
      if (jl1>=0 && jl1<LF && j!=ib) ss1 += a1[jj]*inv1 + 1e-6f;
    }
  }
  ss0=warpSum(ss0); ss1=warpSum(ss1);
  __syncthreads();
  if (lane==0){ float* rr = red + (rg*2+wh)*4; rr[2]=ss0; rr[3]=ss1; }
  __syncthreads();
  float rc0 = aq0 / (rA[2]+rB[2]);
  float rc1 = aq1 / (rA[3]+rB[3]);

  unsigned* sr0 = g_scores + (size_t)m*WROW + (size_t)ia*LF;
  unsigned* sr1 = g_scores + (size_t)m*WROW + (size_t)ib*LF;
  #pragma unroll
  for (int jj=0;jj<7;jj++){
    int j = jslot + (jj<<6);
    bool v = (jj<6) || (jslot<8);
    if (!v) continue;
    int jl0 = j - sameA;
    if (jl0>=0 && jl0<LF){
      unsigned key = 0u;
      if (j != ia){
        float wv = (a0[jj]*inv0 + 1e-6f)*rc0;
        unsigned gi = (unsigned)(m*WROW + ia*LF + jl0);
        key = __float_as_uint(__fdividef(wv, neglogu_at(gi)));
      }
      sr0[jl0] = key;
    }
    int jl1 = j - sameB;
    if (jl1>=0 && jl1<LF){
      unsigned key = 0u;
      if (j != ib){
        float wv = (a1[jj]*inv1 + 1e-6f)*rc1;
        unsigned gi = (unsigned)(m*WROW + ib*LF + jl1);
        key = __float_as_uint(__fdividef(wv, neglogu_at(gi)));
      }
      sr1[jl1] = key;
    }
  }
}

// ----------------------------------------------------------------------------
// Fused select+mask per m: 1024 threads, writes BIT-PACKED mask words.
// ----------------------------------------------------------------------------
#define SELT 1024
#define NWARP 32
#define REGION 2432   // multiple of 32; 31*2432 + 1440 = 76832

__global__ void __launch_bounds__(SELT) selmask_kernel(){
  int m = blockIdx.x, tid = threadIdx.x;
  const unsigned* row = g_scores + (size_t)m*WROW;
  unsigned* mwords = g_maskbits + (size_t)m*NWORD;
  __shared__ unsigned hist[256];
  __shared__ unsigned s_prefix;
  __shared__ int s_krem;
  __shared__ int weq[NWARP];

  unsigned prefix = 0; int krem = KSEL;
  for (int pass=0; pass<4; pass++){
    int shift = 24 - 8*pass;
    unsigned hm = pass ? (0xFFFFFFFFu << (shift+8)) : 0u;
    if (tid < 256) hist[tid] = 0;
    __syncthreads();
    for (int idx=tid; idx<WROW; idx+=SELT){
      unsigned u = row[idx];
      if ((u & hm) == prefix) atomicAdd(&hist[(u>>shift)&0xFFu], 1u);
    }
    __syncthreads();
    if (tid==0){
      int cum = 0, b = 255;
      for (; b>=0; b--){ cum += (int)hist[b]; if (cum >= krem) break; }
      int above = cum - (int)hist[b];
      s_prefix = prefix | ((unsigned)b << shift);
      s_krem = krem - above;
    }
    __syncthreads();
    prefix = s_prefix; krem = s_krem;
    __syncthreads();
  }
  const unsigned T = prefix;
  const int need = krem;

  int lane = tid & 31, w = tid >> 5;
  int lo = w*REGION, hi = min(lo + REGION, WROW);

  int ec = 0;
  for (int idx = lo + lane; idx < hi; idx += 32)
    ec += (row[idx] == T);
  #pragma unroll
  for (int o=16;o>0;o>>=1) ec += __shfl_xor_sync(0xffffffffu, ec, o);
  if (lane==0) weq[w] = ec;
  __syncthreads();
  int base = 0;
  for (int ww=0; ww<w; ww++) base += weq[ww];

  int run = base;
  for (int idx0 = lo; idx0 < hi; idx0 += 32){
    int idx = idx0 + lane;
    unsigned u = row[idx];
    bool eq = (u == T);
    unsigned bal = __ballot_sync(0xffffffffu, eq);
    int rank = run + __popc(bal & ((1u<<lane)-1u));
    bool sel = (u > T) || (eq && rank < need);
    unsigned word = __ballot_sync(0xffffffffu, sel);
    if (lane==0) mwords[idx0 >> 5] = word;
    run += __popc(bal);
  }
}

// ----------------------------------------------------------------------------
// attn kernel v5: block = (m, 8 rows), 128 threads, warp = 2 rows.
// Reads fp16 probs, renormalizes, AV with V line shared across both rows.
// ----------------------------------------------------------------------------
__global__ void __launch_bounds__(128, 8) attn_kernel(){
  int blk = blockIdx.x;
  int m = blk / 49, it = blk % 49;
  int lane = threadIdx.x & 31, w = threadIdx.x >> 5;   // w in 0..3
  int i0 = it*8;
  __shared__ float l[8][Nn];

  const unsigned* mb = g_maskbits + (size_t)m*NWORD;

  #pragma unroll 1
  for (int rr=0; rr<2; rr++){
    int i = i0 + w*2 + rr;
    int same = (i >= LF) ? LF : 0;
    int base_bit = i*LF;
    int w0 = base_bit >> 5, off = base_bit & 31;
    unsigned mw[8];
    #pragma unroll
    for (int k=0;k<8;k++) mw[k] = __ldg(mb + w0 + k);  // +8 pad makes this safe

    const __half* pr = g_probs + ((size_t)m*Nn + i)*Nn;
    float p[13];
    float dsum = 0.f;
    #pragma unroll
    for (int k=0;k<13;k++){
      int j = lane + 32*k;
      float v = (j < Nn) ? __half2float(__ldg(pr + j)) : 0.f;
      int jl = j - same;
      if (jl >= 0 && jl < LF){
        int s0 = off + 32*k - same;
        int wlo = s0 >> 5, sh = s0 & 31;
        unsigned f = __funnelshift_r(mw[wlo], mw[wlo+1], sh);
        if ((f >> lane) & 1u) v = 0.f;
      }
      p[k] = v;
      dsum += v;
    }
    float inv = 1.0f/warpSum(dsum);
    #pragma unroll
    for (int k=0;k<13;k++){
      int j = lane + 32*k;
      if (j < Nn) l[w*2+rr][j] = p[k]*inv;
    }
  }
  __syncwarp();

  const int r0 = w*2, r1 = r0+1;
  const float* vb = g_v + (size_t)m*Nn*HD + lane;
  const float* l0 = l[r0];
  const float* l1 = l[r1];
  float a00=0.f, a01=0.f, a10=0.f, a11=0.f;
  #pragma unroll 2
  for (int j=0; j<Nn; j+=2){
    float v0 = vb[(size_t)j*HD];
    float v1 = vb[(size_t)(j+1)*HD];
    a00 += l0[j]*v0;   a10 += l1[j]*v0;
    a01 += l0[j+1]*v1; a11 += l1[j+1]*v1;
  }
  float acc0 = a00 + a01;
  float acc1 = a10 + a11;

  int b = m >> 4, h = m & 15;
  g_o[((size_t)(b*Nn + (i0+r0)))*Cc + h*HD + lane] = acc0;
  g_o[((size_t)(b*Nn + (i0+r1)))*Cc + h*HD + lane] = acc1;
}

// ----------------------------------------------------------------------------
// Launch
// ----------------------------------------------------------------------------
extern "C" void kernel_launch(void* const* d_in, const int* in_sizes, int n_in,
                              void* d_out, int out_size){
  const float* x      = (const float*)d_in[0];
  const float* n1w    = (const float*)d_in[1];
  const float* n1b    = (const float*)d_in[2];
  const float* qkv_w  = (const float*)d_in[3];
  const float* qkv_b  = (const float*)d_in[4];
  const float* proj_w = (const float*)d_in[5];
  const float* proj_b = (const float*)d_in[6];
  const float* n2w    = (const float*)d_in[7];
  const float* n2b    = (const float*)d_in[8];
  const float* fc1_w  = (const float*)d_in[9];
  const float* fc1_b  = (const float*)d_in[10];
  const float* fc2_w  = (const float*)d_in[11];
  const float* fc2_b  = (const float*)d_in[12];
  float* out = (float*)d_out;

  float *p_h, *p_o, *p_x1, *p_h2, *p_mlp;
  cudaGetSymbolAddress((void**)&p_h,   g_h);
  cudaGetSymbolAddress((void**)&p_o,   g_o);
  cudaGetSymbolAddress((void**)&p_x1,  g_x1);
  cudaGetSymbolAddress((void**)&p_h2,  g_h2);
  cudaGetSymbolAddress((void**)&p_mlp, g_mlp);

  // allow >48KB dynamic smem (idempotent)
  cudaFuncSetAttribute(score_kernel,
                       cudaFuncAttributeMaxDynamicSharedMemorySize, SC_SMEM);
  cudaFuncSetAttribute(gemm_tf32<128,2>,
                       cudaFuncAttributeMaxDynamicSharedMemorySize, GEMM_SMEM_MAX);
  cudaFuncSetAttribute(gemm_tf32<128,1>,
                       cudaFuncAttributeMaxDynamicSharedMemorySize, GEMM_SMEM_MAX);
  cudaFuncSetAttribute(gemm_tf32<64,0>,
                       cudaFuncAttributeMaxDynamicSharedMemorySize, GEMM_SMEM_MAX);

  const int smem128 = (4*AS_STRIDE + 4*16*136)*4;
  const int smem64  = (4*AS_STRIDE + 4*16*72)*4;

  // 1) LN1
  ln_kernel<<<ROWS, 256>>>(x, n1w, n1b, p_h);
  // 2) QKV GEMM with compile-time scatter epilogue (no reorder kernel)
  gemm_tf32<128,2><<<dim3(3*Cc/128, ROWS/128), 256, smem128>>>(p_h, qkv_w, qkv_b,
                                               nullptr, nullptr, ROWS, 3*Cc, Cc);
  // 3) QK (smem-staged, swizzled) + fp16 probs + sort keys
  score_kernel<<<Mm*49, 256, SC_SMEM>>>();
  // 4) fused top-k threshold + bit-packed mask
  selmask_kernel<<<Mm, SELT>>>();
  // 5) renormalize masked fp16 probs + AV
  attn_kernel<<<Mm*49, 128>>>();
  // 6) proj + residual(x)  (BN=64)
  gemm_tf32<64,0><<<dim3(Cc/64, ROWS/128), 256, smem64>>>(p_o, proj_w, proj_b, x, p_x1,
                                             ROWS, Cc, Cc);
  // 7) LN2
  ln_kernel<<<ROWS, 256>>>(p_x1, n2w, n2b, p_h2);
  // 8) fc1 + exact gelu (BN=128)
  gemm_tf32<128,1><<<dim3(MLPH/128, ROWS/128), 256, smem128>>>(p_h2, fc1_w, fc1_b,
                                               nullptr, p_mlp, ROWS, MLPH, Cc);
  // 9) fc2 + residual(x1) -> out  (BN=64)
  gemm_tf32<64,0><<<dim3(Cc/64, ROWS/128), 256, smem64>>>(p_mlp, fc2_w, fc2_b, p_x1, out,
                                             ROWS, Cc, MLPH);
}